// round 8
// baseline (speedup 1.0000x reference)
#include <cuda_runtime.h>

// ---------------- problem constants ----------------
#define O_    2
#define Z_    8
#define OY_   1024
#define P_    8
#define N_    256
#define NB_   32
#define NF    65536
#define TWO_PI 6.28318530717958647692f
#define PI_F  3.14159265358979323846f

// L2-blocking: process the batch in chunks so each chunk's bufA/bufB slices
// (33.5 MB each) stay resident in the 126 MB L2 across the whole z-chain.
#define NCHUNK 8
#define NBC    (NB_ / NCHUNK)    // 4 batch items per chunk

// XOR-swizzled column-tile addressing (8 columns x 256 rows, float2).
#define TADDR(my,j) ((((my) << 3)) | ((j) ^ (((my) >> 2) & 7)))

// ---------------- static device scratch ----------------
__device__ int    g_cy[NB_], g_cx[NB_];
__device__ float  g_sy[NB_], g_sx[NB_];
__device__ float2 g_Ht[(size_t)NF];                                   // H permuted both axes, /256 folded
__device__ __align__(16) float2 g_probeF[(size_t)P_ * NF];            // fft2(probe), permuted axes
__device__ __align__(16) float2 g_probes[(size_t)NB_ * P_ * NF];      // shifted probes (spatial)
__device__ __align__(16) float2 g_bufA[(size_t)NB_ * O_ * P_ * NF];
__device__ __align__(16) float2 g_bufB[(size_t)NB_ * O_ * P_ * NF];

// ---------------- complex helpers ----------------
__device__ __forceinline__ float2 cadd(float2 a, float2 b){ return make_float2(a.x+b.x, a.y+b.y); }
__device__ __forceinline__ float2 csub(float2 a, float2 b){ return make_float2(a.x-b.x, a.y-b.y); }
__device__ __forceinline__ float2 cmul(float2 a, float2 b){ return make_float2(a.x*b.x - a.y*b.y, a.x*b.y + a.y*b.x); }
__device__ __forceinline__ float2 cmulc(float2 t, float2 x){ return make_float2(t.x*x.x + t.y*x.y, t.x*x.y - t.y*x.x); }
__device__ __forceinline__ float2 conjf2(float2 a){ return make_float2(a.x, -a.y); }

__device__ __forceinline__ int rev5(int l){ return (int)(__brev((unsigned)l) >> 27); }
__device__ __forceinline__ int rev3c(int r){ return ((r&1)<<2) | (r&2) | ((r&4)>>2); }
__device__ __forceinline__ int sigma(int m){ return rev3c(m>>5) + 8*rev5(m&31); }
// x-axis frequency permutation at PHYSICAL float2 index q (float4-packed storage)
__device__ __forceinline__ int sigx(int q){ return rev3c(2*(q>>6) + (q&1)) + 8*rev5((q>>1)&31); }

__device__ __forceinline__ float2 shflx(float2 v, int d){
    v.x = __shfl_xor_sync(0xffffffffu, v.x, d);
    v.y = __shfl_xor_sync(0xffffffffu, v.y, d);
    return v;
}

// ---------------- per-lane FFT constants ----------------
struct WF { float2 w16, w8, w4, w2, base; float t16, t8, t4, t2, t1; };
__device__ __forceinline__ WF make_wf(int l){
    WF W; float s, c;
    __sincosf(-(TWO_PI/256.0f)*(float)l, &s, &c); W.base = make_float2(c, s);
    __sincosf(-(PI_F/16.0f)*(float)(l&15), &s, &c); W.w16 = (l&16)? make_float2(c,s) : make_float2(1.f,0.f);
    __sincosf(-(PI_F/ 8.0f)*(float)(l& 7), &s, &c); W.w8  = (l& 8)? make_float2(c,s) : make_float2(1.f,0.f);
    __sincosf(-(PI_F/ 4.0f)*(float)(l& 3), &s, &c); W.w4  = (l& 4)? make_float2(c,s) : make_float2(1.f,0.f);
    __sincosf(-(PI_F/ 2.0f)*(float)(l& 1), &s, &c); W.w2  = (l& 2)? make_float2(c,s) : make_float2(1.f,0.f);
    W.t16 = (l&16)? -1.f:1.f;  W.t8 = (l&8)? -1.f:1.f;  W.t4 = (l&4)? -1.f:1.f;
    W.t2  = (l& 2)? -1.f:1.f;  W.t1 = (l&1)? -1.f:1.f;
    return W;
}

#define RC8 0.70710678118654752440f

// DIF-8 in registers: natural in, bitrev3 out
__device__ __forceinline__ void fft8(float2 v[8]){
    float2 t0=cadd(v[0],v[4]), t1=cadd(v[1],v[5]), t2=cadd(v[2],v[6]), t3=cadd(v[3],v[7]);
    float2 u0=csub(v[0],v[4]);
    float2 d1=csub(v[1],v[5]); float2 u1=make_float2(RC8*(d1.x+d1.y), RC8*(d1.y-d1.x));
    float2 d2=csub(v[2],v[6]); float2 u2=make_float2(d2.y, -d2.x);
    float2 d3=csub(v[3],v[7]); float2 u3=make_float2(RC8*(d3.y-d3.x), -RC8*(d3.x+d3.y));
    float2 a0=cadd(t0,t2), a1=cadd(t1,t3), a2=csub(t0,t2);
    float2 dt=csub(t1,t3); float2 a3=make_float2(dt.y,-dt.x);
    float2 b0=cadd(u0,u2), b1=cadd(u1,u3), b2=csub(u0,u2);
    float2 du=csub(u1,u3); float2 b3=make_float2(du.y,-du.x);
    v[0]=cadd(a0,a1); v[1]=csub(a0,a1); v[2]=cadd(a2,a3); v[3]=csub(a2,a3);
    v[4]=cadd(b0,b1); v[5]=csub(b0,b1); v[6]=cadd(b2,b3); v[7]=csub(b2,b3);
}

// DIT-8 in registers: bitrev3 in, natural out, e^{+}
__device__ __forceinline__ void ifft8(float2 v[8]){
    float2 s0=cadd(v[0],v[1]), d0=csub(v[0],v[1]);
    float2 s1=cadd(v[2],v[3]), d1=csub(v[2],v[3]);
    float2 s2=cadd(v[4],v[5]), d2=csub(v[4],v[5]);
    float2 s3=cadd(v[6],v[7]), d3=csub(v[6],v[7]);
    float2 id1=make_float2(-d1.y,d1.x), id3=make_float2(-d3.y,d3.x);
    float2 p0=cadd(s0,s1), p2=csub(s0,s1), p1=cadd(d0,id1), p3=csub(d0,id1);
    float2 q0=cadd(s2,s3), q2=csub(s2,s3), q1=cadd(d2,id3), q3=csub(d2,id3);
    float2 w1q=make_float2(RC8*(q1.x-q1.y), RC8*(q1.x+q1.y));
    float2 iq2=make_float2(-q2.y,q2.x);
    float2 w3q=make_float2(-RC8*(q3.x+q3.y), RC8*(q3.x-q3.y));
    v[0]=cadd(p0,q0);  v[4]=csub(p0,q0);
    v[1]=cadd(p1,w1q); v[5]=csub(p1,w1q);
    v[2]=cadd(p2,iq2); v[6]=csub(p2,iq2);
    v[3]=cadd(p3,w3q); v[7]=csub(p3,w3q);
}

__device__ __forceinline__ void twchain(float2 v[8], float2 base){
    float2 w = base;
    v[4]=cmul(v[4],w); w=cmul(w,base);
    v[2]=cmul(v[2],w); w=cmul(w,base);
    v[6]=cmul(v[6],w); w=cmul(w,base);
    v[1]=cmul(v[1],w); w=cmul(w,base);
    v[5]=cmul(v[5],w); w=cmul(w,base);
    v[3]=cmul(v[3],w); w=cmul(w,base);
    v[7]=cmul(v[7],w);
}

// ---- select-free cross-lane stages ----
__device__ __forceinline__ void fstage(float2 v[8], int D, float2 w, float t){
    #pragma unroll
    for (int k = 0; k < 8; k++){
        float2 p = shflx(v[k], D);
        float2 u = make_float2(fmaf(t, v[k].x, p.x), fmaf(t, v[k].y, p.y));
        v[k] = cmul(w, u);
    }
}
__device__ __forceinline__ void fstage1(float2 v[8], float t){
    #pragma unroll
    for (int k = 0; k < 8; k++){
        float2 p = shflx(v[k], 1);
        v[k] = make_float2(fmaf(t, v[k].x, p.x), fmaf(t, v[k].y, p.y));
    }
}
__device__ __forceinline__ void istage(float2 v[8], int D, float2 w, float t){
    #pragma unroll
    for (int k = 0; k < 8; k++){
        float2 y = cmulc(w, v[k]);
        float2 p = shflx(y, D);
        v[k] = make_float2(fmaf(t, y.x, p.x), fmaf(t, y.y, p.y));
    }
}
__device__ __forceinline__ void istage1(float2 v[8], float t){
    #pragma unroll
    for (int k = 0; k < 8; k++){
        float2 p = shflx(v[k], 1);
        v[k] = make_float2(fmaf(t, v[k].x, p.x), fmaf(t, v[k].y, p.y));
    }
}

__device__ __forceinline__ void fwd256(float2 v[8], const WF& W){
    fft8(v);
    twchain(v, W.base);
    fstage(v,16,W.w16,W.t16);
    fstage(v, 8,W.w8 ,W.t8 );
    fstage(v, 4,W.w4 ,W.t4 );
    fstage(v, 2,W.w2 ,W.t2 );
    fstage1(v, W.t1);
}
__device__ __forceinline__ void inv256(float2 v[8], const WF& W){
    istage1(v, W.t1);
    istage(v, 2,W.w2 ,W.t2 );
    istage(v, 4,W.w4 ,W.t4 );
    istage(v, 8,W.w8 ,W.t8 );
    istage(v,16,W.w16,W.t16);
    twchain(v, conjf2(W.base));
    ifft8(v);
}

// ---- float4-packed row I/O ----
__device__ __forceinline__ void load8(float2 v[8], const float2* row, int l){
    const float4* r4 = (const float4*)row;
    #pragma unroll
    for (int rp = 0; rp < 4; rp++){
        float4 q = r4[l + 32*rp];
        v[2*rp]   = make_float2(q.x, q.y);
        v[2*rp+1] = make_float2(q.z, q.w);
    }
}
__device__ __forceinline__ void store8(float2* row, const float2 v[8], int l){
    float4* r4 = (float4*)row;
    #pragma unroll
    for (int rp = 0; rp < 4; rp++)
        r4[l + 32*rp] = make_float4(v[2*rp].x, v[2*rp].y, v[2*rp+1].x, v[2*rp+1].y);
}

// ---------------- setup ----------------
__global__ void k_setup(const float* __restrict__ shifts,
                        const int*   __restrict__ crop,
                        const void*  __restrict__ idxraw){
    if (threadIdx.x == 0){
        const int* w = (const int*)idxraw;
        int orr = 0;
        for (int k = 1; k < NB_; k += 2) orr |= w[k];
        bool is64 = (orr == 0);
        for (int b = 0; b < NB_; b++){
            int id = is64 ? (int)(((const long long*)idxraw)[b]) : w[b];
            g_cy[b] = crop[2*id];
            g_cx[b] = crop[2*id + 1];
            g_sy[b] = shifts[2*id];
            g_sx[b] = shifts[2*id + 1];
        }
    }
}

__global__ void k_setup_H(const float* __restrict__ Hr, const float* __restrict__ Hi){
    int idx = blockIdx.x*256 + threadIdx.x;
    int my = idx & 255, mx = idx >> 8;
    int ky = sigma(my), kx = sigx(mx);
    size_t hsrc = (size_t)ky*N_ + kx;
    g_Ht[(size_t)mx*N_ + my] = make_float2(Hr[hsrc]*(1.0f/256.0f), Hi[hsrc]*(1.0f/256.0f));
}

// ---------------- probe fft2 ----------------
__global__ void k_probe_rows(const float* __restrict__ pr, const float* __restrict__ pi){
    int blk = blockIdx.x, rb = blk & 31, p = blk >> 5;
    int w = threadIdx.x >> 5, l = threadIdx.x & 31;
    int y = rb*8 + w;
    WF W = make_wf(l);
    size_t base = ((size_t)p*N_ + y)*N_;
    float2 v[8];
    #pragma unroll
    for (int r = 0; r < 8; r++){ int x = l + 32*r; v[r] = make_float2(pr[base+x], pi[base+x]); }
    fwd256(v, W);
    store8(g_probeF + base, v, l);
}

__global__ void k_probe_cols(){
    __shared__ float2 tile[2048];
    int blk = blockIdx.x, t = blk & 31, p = blk >> 5;
    int xg0 = t*8;
    int w = threadIdx.x >> 5, l = threadIdx.x & 31;
    WF W = make_wf(l);
    float2* F = g_probeF + (size_t)p*NF;
    #pragma unroll
    for (int c = 0; c < 8; c++){
        int e = threadIdx.x + 256*c; int j = e & 7, my = e >> 3;
        tile[TADDR(my,j)] = F[(size_t)my*N_ + xg0 + j];
    }
    __syncthreads();
    float2 v[8];
    #pragma unroll
    for (int r = 0; r < 8; r++) v[r] = tile[TADDR(l+32*r, w)];
    fwd256(v, W);
    #pragma unroll
    for (int r = 0; r < 8; r++) tile[TADDR(l+32*r, w)] = v[r];
    __syncthreads();
    #pragma unroll
    for (int c = 0; c < 8; c++){
        int e = threadIdx.x + 256*c; int j = e & 7, my = e >> 3;
        F[(size_t)my*N_ + xg0 + j] = tile[TADDR(my,j)];
    }
}

// ---------------- shifted probes (chunked over b) ----------------
__global__ void k_probes_rows(int b0){
    int blk = blockIdx.x, rb = blk & 31, bp = blk >> 5;
    int p = bp & 7, b = b0 + (bp >> 3);
    int w = threadIdx.x >> 5, l = threadIdx.x & 31;
    int my = rb*8 + w;
    WF W = make_wf(l);
    float sy = g_sy[b], sx = g_sx[b];
    int ky = sigma(my);
    float f = sy*(float)ky*(1.0f/256.0f) + sx*(float)rev5(l)*(1.0f/32.0f);
    f -= rintf(f);
    float s, c; __sincosf(-TWO_PI*f, &s, &c);
    float2 C = make_float2(c*(1.0f/256.0f), s*(1.0f/256.0f));
    float fb = sx*(1.0f/256.0f); fb -= rintf(fb);
    __sincosf(-TWO_PI*fb, &s, &c); float2 B = make_float2(c, s);
    size_t base = ((size_t)p*N_ + my)*N_;
    float2 v[8];
    load8(v, g_probeF + base, l);
    float2 wv = C;
    v[0]=cmul(v[0],wv); wv=cmul(wv,B);
    v[4]=cmul(v[4],wv); wv=cmul(wv,B);
    v[2]=cmul(v[2],wv); wv=cmul(wv,B);
    v[6]=cmul(v[6],wv); wv=cmul(wv,B);
    v[1]=cmul(v[1],wv); wv=cmul(wv,B);
    v[5]=cmul(v[5],wv); wv=cmul(wv,B);
    v[3]=cmul(v[3],wv); wv=cmul(wv,B);
    v[7]=cmul(v[7],wv);
    inv256(v, W);
    store8(g_probes + ((size_t)b*P_ + p)*NF + (size_t)my*N_, v, l);
}

__global__ void k_probes_cols(int b0){
    __shared__ float2 tile[2048];
    int blk = blockIdx.x, t = blk & 31, fl = blk >> 5;
    int f = b0*P_ + fl;
    int xg0 = t*8;
    int w = threadIdx.x >> 5, l = threadIdx.x & 31;
    WF W = make_wf(l);
    float2* F = g_probes + (size_t)f*NF;
    #pragma unroll
    for (int c = 0; c < 8; c++){
        int e = threadIdx.x + 256*c; int j = e & 7, my = e >> 3;
        tile[TADDR(my,j)] = F[(size_t)my*N_ + xg0 + j];
    }
    __syncthreads();
    float2 v[8];
    #pragma unroll
    for (int r = 0; r < 8; r++) v[r] = tile[TADDR(l+32*r, w)];
    inv256(v, W);
    #pragma unroll
    for (int r = 0; r < 8; r++){
        v[r].x *= (1.0f/256.0f); v[r].y *= (1.0f/256.0f);
        tile[TADDR(l+32*r, w)] = v[r];
    }
    __syncthreads();
    #pragma unroll
    for (int c = 0; c < 8; c++){
        int e = threadIdx.x + 256*c; int j = e & 7, my = e >> 3;
        F[(size_t)my*N_ + xg0 + j] = tile[TADDR(my,j)];
    }
}

// ---------------- rows pass A (chunked) ----------------
__global__ void k_rows_A(const float* __restrict__ obja, const float* __restrict__ objp,
                         float* __restrict__ pp_out, int z, int b0){
    int blk = blockIdx.x, rb = blk & 31, bol = blk >> 5;
    int o = bol & 1, b = b0 + (bol >> 1);
    int bo = b*O_ + o;
    int w = threadIdx.x >> 5, l = threadIdx.x & 31;
    int y = rb*8 + w;
    WF W = make_wf(l);
    int cy = g_cy[b], cx = g_cx[b];
    size_t obase = ((size_t)(o*Z_ + z)*OY_ + (size_t)(cy + y))*OY_ + cx;
    float scale = (z == 0) ? 1.0f : (1.0f/256.0f);
    size_t ppbase = ((((size_t)b*O_ + o)*Z_ + z)*N_ + y)*(size_t)N_;
    float2 obj[8];
    #pragma unroll
    for (int r = 0; r < 8; r++){
        int x = l + 32*r;
        float A = obja[obase + x], ph = objp[obase + x];
        float sn, cs; __sincosf(ph, &sn, &cs);
        obj[r] = make_float2(A*cs*scale, A*sn*scale);
        pp_out[ppbase + x] = ph;
    }
    for (int p = 0; p < P_; p++){
        const float2* src = (z == 0)
            ? g_probes + ((size_t)b*P_ + p)*NF + (size_t)y*N_
            : g_bufB  + ((size_t)bo*P_ + p)*NF + (size_t)y*N_;
        float2 v[8];
        load8(v, src, l);
        if (z) inv256(v, W);
        #pragma unroll
        for (int r = 0; r < 8; r++) v[r] = cmul(v[r], obj[r]);
        fwd256(v, W);
        store8(g_bufA + ((size_t)bo*P_ + p)*NF + (size_t)y*N_, v, l);
    }
}

// ---------------- cols pass B (chunked) ----------------
__global__ void k_cols_H(int b0){
    __shared__ float2 tile[2048];
    int blk = blockIdx.x, t = blk & 31, fl = blk >> 5;
    int f = b0*O_*P_ + fl;
    int xg0 = t*8;
    int w = threadIdx.x >> 5, l = threadIdx.x & 31;
    WF W = make_wf(l);
    const float2* s = g_bufA + (size_t)f*NF;
    #pragma unroll
    for (int c = 0; c < 8; c++){
        int e = threadIdx.x + 256*c; int j = e & 7, my = e >> 3;
        tile[TADDR(my,j)] = s[(size_t)my*N_ + xg0 + j];
    }
    __syncthreads();
    float2 v[8];
    #pragma unroll
    for (int r = 0; r < 8; r++) v[r] = tile[TADDR(l+32*r, w)];
    fwd256(v, W);
    const float2* Hc = g_Ht + (size_t)(xg0 + w)*N_;
    #pragma unroll
    for (int r = 0; r < 8; r++) v[r] = cmul(v[r], Hc[l + 32*r]);
    inv256(v, W);
    #pragma unroll
    for (int r = 0; r < 8; r++) tile[TADDR(l+32*r, w)] = v[r];
    __syncthreads();
    float2* d = g_bufB + (size_t)f*NF;
    #pragma unroll
    for (int c = 0; c < 8; c++){
        int e = threadIdx.x + 256*c; int j = e & 7, my = e >> 3;
        d[(size_t)my*N_ + xg0 + j] = tile[TADDR(my,j)];
    }
}

// ---------------- final (chunked) ----------------
__global__ void k_cols_final(const float* __restrict__ occu, float* __restrict__ dp, int b0){
    __shared__ float2 tile[2048];
    int blk = blockIdx.x, t = blk & 31, b = b0 + (blk >> 5);
    int xg0 = t*8;
    int w = threadIdx.x >> 5, l = threadIdx.x & 31;
    WF W = make_wf(l);
    float acc[8];
    #pragma unroll
    for (int k = 0; k < 8; k++) acc[k] = 0.0f;
    for (int o = 0; o < O_; o++){
        float wt = occu[o];
        for (int p = 0; p < P_; p++){
            const float2* s = g_bufA + ((size_t)((b*O_ + o)*P_ + p))*NF;
            __syncthreads();
            #pragma unroll
            for (int c = 0; c < 8; c++){
                int e = threadIdx.x + 256*c; int j = e & 7, my = e >> 3;
                tile[TADDR(my,j)] = s[(size_t)my*N_ + xg0 + j];
            }
            __syncthreads();
            float2 v[8];
            #pragma unroll
            for (int r = 0; r < 8; r++) v[r] = tile[TADDR(l+32*r, w)];
            fwd256(v, W);
            #pragma unroll
            for (int r = 0; r < 8; r++) acc[r] += wt*(v[r].x*v[r].x + v[r].y*v[r].y);
        }
    }
    int kx = sigx(xg0 + w);
    int xs = (kx + 128) & 255;
    int r5 = rev5(l);
    #pragma unroll
    for (int r = 0; r < 8; r++){
        int ky = rev3c(r) + 8*r5;
        dp[(size_t)b*NF + (size_t)((ky + 128) & 255)*N_ + xs] = acc[r];
    }
}

// ---------------- launch ----------------
extern "C" void kernel_launch(void* const* d_in, const int* in_sizes, int n_in,
                              void* d_out, int out_size){
    const float* obja   = (const float*)d_in[0];
    const float* objp   = (const float*)d_in[1];
    const float* pr     = (const float*)d_in[2];
    const float* pi     = (const float*)d_in[3];
    const float* Hr     = (const float*)d_in[4];
    const float* Hi     = (const float*)d_in[5];
    const float* occu   = (const float*)d_in[6];
    const float* shifts = (const float*)d_in[7];
    const int*   crop   = (const int*)d_in[8];
    const void*  idx    = d_in[9];

    float* dp = (float*)d_out;                    // (NB, 256, 256)
    float* pp = dp + (size_t)NB_ * NF;            // (NB, O, Z, 256, 256)

    k_setup<<<1, 32>>>(shifts, crop, idx);
    k_setup_H<<<256, 256>>>(Hr, Hi);
    k_probe_rows<<<P_*32, 256>>>(pr, pi);
    k_probe_cols<<<P_*32, 256>>>();

    // L2-blocked chunks: full probe-shift + z-chain + reduction per NBC batch items
    for (int c = 0; c < NCHUNK; c++){
        int b0 = c * NBC;
        k_probes_rows<<<NBC*P_*32, 256>>>(b0);
        k_probes_cols<<<NBC*P_*32, 256>>>(b0);
        k_rows_A<<<NBC*O_*32, 256>>>(obja, objp, pp, 0, b0);
        for (int z = 0; z < Z_ - 1; z++){
            k_cols_H<<<NBC*O_*P_*32, 256>>>(b0);
            k_rows_A<<<NBC*O_*32, 256>>>(obja, objp, pp, z + 1, b0);
        }
        k_cols_final<<<NBC*32, 256>>>(occu, dp, b0);
    }
}

// round 9
// speedup vs baseline: 1.2225x; 1.2225x over previous
#include <cuda_runtime.h>

// ---------------- problem constants ----------------
#define O_    2
#define Z_    8
#define OY_   1024
#define P_    8
#define N_    256
#define NB_   32
#define NF    65536
#define TWO_PI 6.28318530717958647692f
#define PI_F  3.14159265358979323846f

// XOR-swizzled column-tile addressing (8 columns x 256 rows, float2).
#define TADDR(my,j) ((((my) << 3)) | ((j) ^ (((my) >> 2) & 7)))

// ---------------- static device scratch ----------------
__device__ int    g_cy[NB_], g_cx[NB_];
__device__ float  g_sy[NB_], g_sx[NB_];
__device__ float2 g_Ht[(size_t)NF];                                   // H permuted both axes, /256 folded
__device__ __align__(16) float2 g_probeF[(size_t)P_ * NF];            // fft2(probe), permuted axes
__device__ __align__(16) float2 g_probes[(size_t)NB_ * P_ * NF];      // shifted probes (spatial)
__device__ __align__(16) float2 g_bufA[(size_t)NB_ * O_ * P_ * NF];
__device__ __align__(16) float2 g_bufB[(size_t)NB_ * O_ * P_ * NF];

// ---------------- complex helpers ----------------
__device__ __forceinline__ float2 cadd(float2 a, float2 b){ return make_float2(a.x+b.x, a.y+b.y); }
__device__ __forceinline__ float2 csub(float2 a, float2 b){ return make_float2(a.x-b.x, a.y-b.y); }
__device__ __forceinline__ float2 cmul(float2 a, float2 b){ return make_float2(a.x*b.x - a.y*b.y, a.x*b.y + a.y*b.x); }
__device__ __forceinline__ float2 cmulc(float2 t, float2 x){ return make_float2(t.x*x.x + t.y*x.y, t.x*x.y - t.y*x.x); }
__device__ __forceinline__ float2 conjf2(float2 a){ return make_float2(a.x, -a.y); }

__device__ __forceinline__ int rev5(int l){ return (int)(__brev((unsigned)l) >> 27); }
__device__ __forceinline__ int rev3c(int r){ return ((r&1)<<2) | (r&2) | ((r&4)>>2); }
__device__ __forceinline__ int sigma(int m){ return rev3c(m>>5) + 8*rev5(m&31); }
// x-axis frequency permutation at PHYSICAL float2 index q (float4-packed storage)
__device__ __forceinline__ int sigx(int q){ return rev3c(2*(q>>6) + (q&1)) + 8*rev5((q>>1)&31); }

__device__ __forceinline__ float2 shflx(float2 v, int d){
    v.x = __shfl_xor_sync(0xffffffffu, v.x, d);
    v.y = __shfl_xor_sync(0xffffffffu, v.y, d);
    return v;
}

// ---------------- per-lane FFT constants ----------------
struct WF { float2 w16, w8, w4, w2, base; float t16, t8, t4, t2, t1; };
__device__ __forceinline__ WF make_wf(int l){
    WF W; float s, c;
    __sincosf(-(TWO_PI/256.0f)*(float)l, &s, &c); W.base = make_float2(c, s);
    __sincosf(-(PI_F/16.0f)*(float)(l&15), &s, &c); W.w16 = (l&16)? make_float2(c,s) : make_float2(1.f,0.f);
    __sincosf(-(PI_F/ 8.0f)*(float)(l& 7), &s, &c); W.w8  = (l& 8)? make_float2(c,s) : make_float2(1.f,0.f);
    __sincosf(-(PI_F/ 4.0f)*(float)(l& 3), &s, &c); W.w4  = (l& 4)? make_float2(c,s) : make_float2(1.f,0.f);
    __sincosf(-(PI_F/ 2.0f)*(float)(l& 1), &s, &c); W.w2  = (l& 2)? make_float2(c,s) : make_float2(1.f,0.f);
    W.t16 = (l&16)? -1.f:1.f;  W.t8 = (l&8)? -1.f:1.f;  W.t4 = (l&4)? -1.f:1.f;
    W.t2  = (l& 2)? -1.f:1.f;  W.t1 = (l&1)? -1.f:1.f;
    return W;
}

#define RC8 0.70710678118654752440f

// DIF-8 in registers: natural in, bitrev3 out
__device__ __forceinline__ void fft8(float2 v[8]){
    float2 t0=cadd(v[0],v[4]), t1=cadd(v[1],v[5]), t2=cadd(v[2],v[6]), t3=cadd(v[3],v[7]);
    float2 u0=csub(v[0],v[4]);
    float2 d1=csub(v[1],v[5]); float2 u1=make_float2(RC8*(d1.x+d1.y), RC8*(d1.y-d1.x));
    float2 d2=csub(v[2],v[6]); float2 u2=make_float2(d2.y, -d2.x);
    float2 d3=csub(v[3],v[7]); float2 u3=make_float2(RC8*(d3.y-d3.x), -RC8*(d3.x+d3.y));
    float2 a0=cadd(t0,t2), a1=cadd(t1,t3), a2=csub(t0,t2);
    float2 dt=csub(t1,t3); float2 a3=make_float2(dt.y,-dt.x);
    float2 b0=cadd(u0,u2), b1=cadd(u1,u3), b2=csub(u0,u2);
    float2 du=csub(u1,u3); float2 b3=make_float2(du.y,-du.x);
    v[0]=cadd(a0,a1); v[1]=csub(a0,a1); v[2]=cadd(a2,a3); v[3]=csub(a2,a3);
    v[4]=cadd(b0,b1); v[5]=csub(b0,b1); v[6]=cadd(b2,b3); v[7]=csub(b2,b3);
}

// DIT-8 in registers: bitrev3 in, natural out, e^{+}
__device__ __forceinline__ void ifft8(float2 v[8]){
    float2 s0=cadd(v[0],v[1]), d0=csub(v[0],v[1]);
    float2 s1=cadd(v[2],v[3]), d1=csub(v[2],v[3]);
    float2 s2=cadd(v[4],v[5]), d2=csub(v[4],v[5]);
    float2 s3=cadd(v[6],v[7]), d3=csub(v[6],v[7]);
    float2 id1=make_float2(-d1.y,d1.x), id3=make_float2(-d3.y,d3.x);
    float2 p0=cadd(s0,s1), p2=csub(s0,s1), p1=cadd(d0,id1), p3=csub(d0,id1);
    float2 q0=cadd(s2,s3), q2=csub(s2,s3), q1=cadd(d2,id3), q3=csub(d2,id3);
    float2 w1q=make_float2(RC8*(q1.x-q1.y), RC8*(q1.x+q1.y));
    float2 iq2=make_float2(-q2.y,q2.x);
    float2 w3q=make_float2(-RC8*(q3.x+q3.y), RC8*(q3.x-q3.y));
    v[0]=cadd(p0,q0);  v[4]=csub(p0,q0);
    v[1]=cadd(p1,w1q); v[5]=csub(p1,w1q);
    v[2]=cadd(p2,iq2); v[6]=csub(p2,iq2);
    v[3]=cadd(p3,w3q); v[7]=csub(p3,w3q);
}

__device__ __forceinline__ void twchain(float2 v[8], float2 base){
    float2 w = base;
    v[4]=cmul(v[4],w); w=cmul(w,base);
    v[2]=cmul(v[2],w); w=cmul(w,base);
    v[6]=cmul(v[6],w); w=cmul(w,base);
    v[1]=cmul(v[1],w); w=cmul(w,base);
    v[5]=cmul(v[5],w); w=cmul(w,base);
    v[3]=cmul(v[3],w); w=cmul(w,base);
    v[7]=cmul(v[7],w);
}

// ---- select-free cross-lane stages ----
__device__ __forceinline__ void fstage(float2 v[8], int D, float2 w, float t){
    #pragma unroll
    for (int k = 0; k < 8; k++){
        float2 p = shflx(v[k], D);
        float2 u = make_float2(fmaf(t, v[k].x, p.x), fmaf(t, v[k].y, p.y));
        v[k] = cmul(w, u);
    }
}
__device__ __forceinline__ void fstage1(float2 v[8], float t){
    #pragma unroll
    for (int k = 0; k < 8; k++){
        float2 p = shflx(v[k], 1);
        v[k] = make_float2(fmaf(t, v[k].x, p.x), fmaf(t, v[k].y, p.y));
    }
}
__device__ __forceinline__ void istage(float2 v[8], int D, float2 w, float t){
    #pragma unroll
    for (int k = 0; k < 8; k++){
        float2 y = cmulc(w, v[k]);
        float2 p = shflx(y, D);
        v[k] = make_float2(fmaf(t, y.x, p.x), fmaf(t, y.y, p.y));
    }
}
__device__ __forceinline__ void istage1(float2 v[8], float t){
    #pragma unroll
    for (int k = 0; k < 8; k++){
        float2 p = shflx(v[k], 1);
        v[k] = make_float2(fmaf(t, v[k].x, p.x), fmaf(t, v[k].y, p.y));
    }
}

__device__ __forceinline__ void fwd256(float2 v[8], const WF& W){
    fft8(v);
    twchain(v, W.base);
    fstage(v,16,W.w16,W.t16);
    fstage(v, 8,W.w8 ,W.t8 );
    fstage(v, 4,W.w4 ,W.t4 );
    fstage(v, 2,W.w2 ,W.t2 );
    fstage1(v, W.t1);
}
__device__ __forceinline__ void inv256(float2 v[8], const WF& W){
    istage1(v, W.t1);
    istage(v, 2,W.w2 ,W.t2 );
    istage(v, 4,W.w4 ,W.t4 );
    istage(v, 8,W.w8 ,W.t8 );
    istage(v,16,W.w16,W.t16);
    twchain(v, conjf2(W.base));
    ifft8(v);
}

// ---- float4-packed row I/O ----
__device__ __forceinline__ void load8(float2 v[8], const float2* row, int l){
    const float4* r4 = (const float4*)row;
    #pragma unroll
    for (int rp = 0; rp < 4; rp++){
        float4 q = r4[l + 32*rp];
        v[2*rp]   = make_float2(q.x, q.y);
        v[2*rp+1] = make_float2(q.z, q.w);
    }
}
__device__ __forceinline__ void store8(float2* row, const float2 v[8], int l){
    float4* r4 = (float4*)row;
    #pragma unroll
    for (int rp = 0; rp < 4; rp++)
        r4[l + 32*rp] = make_float4(v[2*rp].x, v[2*rp].y, v[2*rp+1].x, v[2*rp+1].y);
}

// ---------------- setup (merged: H permute + index resolution) ----------------
__global__ void k_setup_H(const float* __restrict__ Hr, const float* __restrict__ Hi,
                          const float* __restrict__ shifts,
                          const int*   __restrict__ crop,
                          const void*  __restrict__ idxraw){
    int idx = blockIdx.x*256 + threadIdx.x;
    int my = idx & 255, mx = idx >> 8;
    int ky = sigma(my), kx = sigx(mx);
    size_t hsrc = (size_t)ky*N_ + kx;
    g_Ht[(size_t)mx*N_ + my] = make_float2(Hr[hsrc]*(1.0f/256.0f), Hi[hsrc]*(1.0f/256.0f));
    if (idx == 0){
        const int* w = (const int*)idxraw;
        int orr = 0;
        for (int k = 1; k < NB_; k += 2) orr |= w[k];
        bool is64 = (orr == 0);
        for (int b = 0; b < NB_; b++){
            int id = is64 ? (int)(((const long long*)idxraw)[b]) : w[b];
            g_cy[b] = crop[2*id];
            g_cx[b] = crop[2*id + 1];
            g_sy[b] = shifts[2*id];
            g_sx[b] = shifts[2*id + 1];
        }
    }
}

// ---------------- probe fft2 ----------------
__global__ void k_probe_rows(const float* __restrict__ pr, const float* __restrict__ pi){
    int blk = blockIdx.x, rb = blk & 31, p = blk >> 5;
    int w = threadIdx.x >> 5, l = threadIdx.x & 31;
    int y = rb*8 + w;
    WF W = make_wf(l);
    size_t base = ((size_t)p*N_ + y)*N_;
    float2 v[8];
    #pragma unroll
    for (int r = 0; r < 8; r++){ int x = l + 32*r; v[r] = make_float2(pr[base+x], pi[base+x]); }
    fwd256(v, W);
    store8(g_probeF + base, v, l);
}

__global__ void k_probe_cols(){
    __shared__ float2 tile[2048];
    int blk = blockIdx.x, t = blk & 31, p = blk >> 5;
    int xg0 = t*8;
    int w = threadIdx.x >> 5, l = threadIdx.x & 31;
    WF W = make_wf(l);
    float2* F = g_probeF + (size_t)p*NF;
    #pragma unroll
    for (int c = 0; c < 8; c++){
        int e = threadIdx.x + 256*c; int j = e & 7, my = e >> 3;
        tile[TADDR(my,j)] = F[(size_t)my*N_ + xg0 + j];
    }
    __syncthreads();
    float2 v[8];
    #pragma unroll
    for (int r = 0; r < 8; r++) v[r] = tile[TADDR(l+32*r, w)];
    fwd256(v, W);
    #pragma unroll
    for (int r = 0; r < 8; r++) tile[TADDR(l+32*r, w)] = v[r];
    __syncthreads();
    #pragma unroll
    for (int c = 0; c < 8; c++){
        int e = threadIdx.x + 256*c; int j = e & 7, my = e >> 3;
        F[(size_t)my*N_ + xg0 + j] = tile[TADDR(my,j)];
    }
}

// ---------------- shifted probes ----------------
__global__ void k_probes_rows(){
    int blk = blockIdx.x, rb = blk & 31, bp = blk >> 5;
    int p = bp & 7, b = bp >> 3;
    int w = threadIdx.x >> 5, l = threadIdx.x & 31;
    int my = rb*8 + w;
    WF W = make_wf(l);
    float sy = g_sy[b], sx = g_sx[b];
    int ky = sigma(my);
    float f = sy*(float)ky*(1.0f/256.0f) + sx*(float)rev5(l)*(1.0f/32.0f);
    f -= rintf(f);
    float s, c; __sincosf(-TWO_PI*f, &s, &c);
    float2 C = make_float2(c*(1.0f/256.0f), s*(1.0f/256.0f));
    float fb = sx*(1.0f/256.0f); fb -= rintf(fb);
    __sincosf(-TWO_PI*fb, &s, &c); float2 B = make_float2(c, s);
    size_t base = ((size_t)p*N_ + my)*N_;
    float2 v[8];
    load8(v, g_probeF + base, l);
    float2 wv = C;
    v[0]=cmul(v[0],wv); wv=cmul(wv,B);
    v[4]=cmul(v[4],wv); wv=cmul(wv,B);
    v[2]=cmul(v[2],wv); wv=cmul(wv,B);
    v[6]=cmul(v[6],wv); wv=cmul(wv,B);
    v[1]=cmul(v[1],wv); wv=cmul(wv,B);
    v[5]=cmul(v[5],wv); wv=cmul(wv,B);
    v[3]=cmul(v[3],wv); wv=cmul(wv,B);
    v[7]=cmul(v[7],wv);
    inv256(v, W);
    store8(g_probes + ((size_t)b*P_ + p)*NF + (size_t)my*N_, v, l);
}

__global__ void k_probes_cols(){
    __shared__ float2 tile[2048];
    int blk = blockIdx.x, t = blk & 31, f = blk >> 5;
    int xg0 = t*8;
    int w = threadIdx.x >> 5, l = threadIdx.x & 31;
    WF W = make_wf(l);
    float2* F = g_probes + (size_t)f*NF;
    #pragma unroll
    for (int c = 0; c < 8; c++){
        int e = threadIdx.x + 256*c; int j = e & 7, my = e >> 3;
        tile[TADDR(my,j)] = F[(size_t)my*N_ + xg0 + j];
    }
    __syncthreads();
    float2 v[8];
    #pragma unroll
    for (int r = 0; r < 8; r++) v[r] = tile[TADDR(l+32*r, w)];
    inv256(v, W);
    #pragma unroll
    for (int r = 0; r < 8; r++){
        v[r].x *= (1.0f/256.0f); v[r].y *= (1.0f/256.0f);
        tile[TADDR(l+32*r, w)] = v[r];
    }
    __syncthreads();
    #pragma unroll
    for (int c = 0; c < 8; c++){
        int e = threadIdx.x + 256*c; int j = e & 7, my = e >> 3;
        F[(size_t)my*N_ + xg0 + j] = tile[TADDR(my,j)];
    }
}

// ---------------- rows pass A (software-pipelined p-loop) ----------------
__global__ void k_rows_A(const float* __restrict__ obja, const float* __restrict__ objp,
                         float* __restrict__ pp_out, int z){
    int blk = blockIdx.x, rb = blk & 31, bo = blk >> 5;
    int o = bo & 1, b = bo >> 1;
    int w = threadIdx.x >> 5, l = threadIdx.x & 31;
    int y = rb*8 + w;
    WF W = make_wf(l);
    int cy = g_cy[b], cx = g_cx[b];
    size_t obase = ((size_t)(o*Z_ + z)*OY_ + (size_t)(cy + y))*OY_ + cx;
    float scale = (z == 0) ? 1.0f : (1.0f/256.0f);
    size_t ppbase = ((((size_t)b*O_ + o)*Z_ + z)*N_ + y)*(size_t)N_;
    float2 obj[8];
    #pragma unroll
    for (int r = 0; r < 8; r++){
        int x = l + 32*r;
        float A = obja[obase + x], ph = objp[obase + x];
        float sn, cs; __sincosf(ph, &sn, &cs);
        obj[r] = make_float2(A*cs*scale, A*sn*scale);
        pp_out[ppbase + x] = ph;
    }
    const float2* srcbase = (z == 0)
        ? g_probes + (size_t)b*P_*NF + (size_t)y*N_
        : g_bufB  + (size_t)bo*P_*NF + (size_t)y*N_;
    float2* dstbase = g_bufA + (size_t)bo*P_*NF + (size_t)y*N_;

    float2 vn[8];
    load8(vn, srcbase, l);                      // prefetch p=0
    #pragma unroll
    for (int p = 0; p < P_; p++){
        float2 v[8];
        #pragma unroll
        for (int r = 0; r < 8; r++) v[r] = vn[r];
        if (p < P_-1) load8(vn, srcbase + (size_t)(p+1)*NF, l);   // prefetch next field
        if (z) inv256(v, W);
        #pragma unroll
        for (int r = 0; r < 8; r++) v[r] = cmul(v[r], obj[r]);
        fwd256(v, W);
        store8(dstbase + (size_t)p*NF, v, l);
    }
}

// ---------------- cols pass B ----------------
__global__ void k_cols_H(){
    __shared__ float2 tile[2048];
    int blk = blockIdx.x, t = blk & 31, f = blk >> 5;
    int xg0 = t*8;
    int w = threadIdx.x >> 5, l = threadIdx.x & 31;
    WF W = make_wf(l);
    const float2* s = g_bufA + (size_t)f*NF;
    #pragma unroll
    for (int c = 0; c < 8; c++){
        int e = threadIdx.x + 256*c; int j = e & 7, my = e >> 3;
        tile[TADDR(my,j)] = s[(size_t)my*N_ + xg0 + j];
    }
    __syncthreads();
    float2 v[8];
    #pragma unroll
    for (int r = 0; r < 8; r++) v[r] = tile[TADDR(l+32*r, w)];
    fwd256(v, W);
    const float2* Hc = g_Ht + (size_t)(xg0 + w)*N_;
    #pragma unroll
    for (int r = 0; r < 8; r++) v[r] = cmul(v[r], Hc[l + 32*r]);
    inv256(v, W);
    #pragma unroll
    for (int r = 0; r < 8; r++) tile[TADDR(l+32*r, w)] = v[r];
    __syncthreads();
    float2* d = g_bufB + (size_t)f*NF;
    #pragma unroll
    for (int c = 0; c < 8; c++){
        int e = threadIdx.x + 256*c; int j = e & 7, my = e >> 3;
        d[(size_t)my*N_ + xg0 + j] = tile[TADDR(my,j)];
    }
}

// ---------------- final ----------------
__global__ void k_cols_final(const float* __restrict__ occu, float* __restrict__ dp){
    __shared__ float2 tile[2048];
    int blk = blockIdx.x, t = blk & 31, b = blk >> 5;
    int xg0 = t*8;
    int w = threadIdx.x >> 5, l = threadIdx.x & 31;
    WF W = make_wf(l);
    float acc[8];
    #pragma unroll
    for (int k = 0; k < 8; k++) acc[k] = 0.0f;
    for (int o = 0; o < O_; o++){
        float wt = occu[o];
        for (int p = 0; p < P_; p++){
            const float2* s = g_bufA + ((size_t)((b*O_ + o)*P_ + p))*NF;
            __syncthreads();
            #pragma unroll
            for (int c = 0; c < 8; c++){
                int e = threadIdx.x + 256*c; int j = e & 7, my = e >> 3;
                tile[TADDR(my,j)] = s[(size_t)my*N_ + xg0 + j];
            }
            __syncthreads();
            float2 v[8];
            #pragma unroll
            for (int r = 0; r < 8; r++) v[r] = tile[TADDR(l+32*r, w)];
            fwd256(v, W);
            #pragma unroll
            for (int r = 0; r < 8; r++) acc[r] += wt*(v[r].x*v[r].x + v[r].y*v[r].y);
        }
    }
    int kx = sigx(xg0 + w);
    int xs = (kx + 128) & 255;
    int r5 = rev5(l);
    #pragma unroll
    for (int r = 0; r < 8; r++){
        int ky = rev3c(r) + 8*r5;
        dp[(size_t)b*NF + (size_t)((ky + 128) & 255)*N_ + xs] = acc[r];
    }
}

// ---------------- launch ----------------
extern "C" void kernel_launch(void* const* d_in, const int* in_sizes, int n_in,
                              void* d_out, int out_size){
    const float* obja   = (const float*)d_in[0];
    const float* objp   = (const float*)d_in[1];
    const float* pr     = (const float*)d_in[2];
    const float* pi     = (const float*)d_in[3];
    const float* Hr     = (const float*)d_in[4];
    const float* Hi     = (const float*)d_in[5];
    const float* occu   = (const float*)d_in[6];
    const float* shifts = (const float*)d_in[7];
    const int*   crop   = (const int*)d_in[8];
    const void*  idx    = d_in[9];

    float* dp = (float*)d_out;                    // (NB, 256, 256)
    float* pp = dp + (size_t)NB_ * NF;            // (NB, O, Z, 256, 256)

    k_setup_H<<<256, 256>>>(Hr, Hi, shifts, crop, idx);   // launch 1
    k_probe_rows<<<P_*32, 256>>>(pr, pi);                  // 2
    k_probe_cols<<<P_*32, 256>>>();                        // 3
    k_probes_rows<<<NB_*P_*32, 256>>>();                   // 4
    k_probes_cols<<<NB_*P_*32, 256>>>();                   // 5

    k_rows_A<<<NB_*O_*32, 256>>>(obja, objp, pp, 0);       // 6 <- ncu -s 5 captures this
    for (int z = 0; z < Z_ - 1; z++){
        k_cols_H<<<NB_*O_*P_*32, 256>>>();
        k_rows_A<<<NB_*O_*32, 256>>>(obja, objp, pp, z + 1);
    }
    k_cols_final<<<NB_*32, 256>>>(occu, dp);
}

// round 10
// speedup vs baseline: 1.2440x; 1.0176x over previous
#include <cuda_runtime.h>

// ---------------- problem constants ----------------
#define O_    2
#define Z_    8
#define OY_   1024
#define P_    8
#define N_    256
#define NB_   32
#define NF    65536
#define TWO_PI 6.28318530717958647692f
#define PI_F  3.14159265358979323846f

// XOR-swizzled column-tile addressing (8 columns x 256 rows, float2).
#define TADDR(my,j) ((((my) << 3)) | ((j) ^ (((my) >> 2) & 7)))

// ---------------- static device scratch ----------------
__device__ int    g_cy[NB_], g_cx[NB_];
__device__ float  g_sy[NB_], g_sx[NB_];
__device__ float2 g_Ht[(size_t)NF];                                   // H permuted both axes, /256 folded
__device__ __align__(16) float2 g_probeF[(size_t)P_ * NF];            // fft2(probe), permuted axes
__device__ __align__(16) float2 g_probes[(size_t)NB_ * P_ * NF];      // shifted probes (spatial)
__device__ __align__(16) float2 g_bufA[(size_t)NB_ * O_ * P_ * NF];
__device__ __align__(16) float2 g_bufB[(size_t)NB_ * O_ * P_ * NF];

// ---------------- packed f32x2 complex helpers (Blackwell FFMA2/FADD2) ----------------
__device__ __forceinline__ float2 cadd(float2 a, float2 b){
    float2 r;
    asm("{\n\t.reg .b64 ra, rb, rr;\n\t"
        "mov.b64 ra, {%2,%3};\n\t"
        "mov.b64 rb, {%4,%5};\n\t"
        "add.rn.f32x2 rr, ra, rb;\n\t"
        "mov.b64 {%0,%1}, rr;\n\t}"
        : "=f"(r.x), "=f"(r.y) : "f"(a.x), "f"(a.y), "f"(b.x), "f"(b.y));
    return r;
}
// a - b  ==  fma(b, {-1,-1}, a)   (product exact, rounding identical to scalar sub)
__device__ __forceinline__ float2 csub(float2 a, float2 b){
    float2 r;
    asm("{\n\t.reg .b64 ra, rb, rn, rr;\n\t"
        "mov.b64 ra, {%2,%3};\n\t"
        "mov.b64 rb, {%4,%5};\n\t"
        "mov.b64 rn, 0xBF800000BF800000;\n\t"
        "fma.rn.f32x2 rr, rb, rn, ra;\n\t"
        "mov.b64 {%0,%1}, rr;\n\t}"
        : "=f"(r.x), "=f"(r.y) : "f"(a.x), "f"(a.y), "f"(b.x), "f"(b.y));
    return r;
}
// r = p + t*v  with scalar t (per-lane +-1), one packed FMA
__device__ __forceinline__ float2 cfma1(float t, float2 v, float2 p){
    float2 r;
    asm("{\n\t.reg .b64 rv, rp, rt, rr;\n\t"
        "mov.b64 rv, {%3,%4};\n\t"
        "mov.b64 rp, {%5,%6};\n\t"
        "mov.b64 rt, {%2,%2};\n\t"
        "fma.rn.f32x2 rr, rv, rt, rp;\n\t"
        "mov.b64 {%0,%1}, rr;\n\t}"
        : "=f"(r.x), "=f"(r.y) : "f"(t), "f"(v.x), "f"(v.y), "f"(p.x), "f"(p.y));
    return r;
}
// scalar complex multiply (packed form needs swap-MOVs; scalar 4-instr is optimal)
__device__ __forceinline__ float2 cmul(float2 a, float2 b){ return make_float2(a.x*b.x - a.y*b.y, a.x*b.y + a.y*b.x); }
__device__ __forceinline__ float2 cmulc(float2 t, float2 x){ return make_float2(t.x*x.x + t.y*x.y, t.x*x.y - t.y*x.x); }
__device__ __forceinline__ float2 conjf2(float2 a){ return make_float2(a.x, -a.y); }

__device__ __forceinline__ int rev5(int l){ return (int)(__brev((unsigned)l) >> 27); }
__device__ __forceinline__ int rev3c(int r){ return ((r&1)<<2) | (r&2) | ((r&4)>>2); }
__device__ __forceinline__ int sigma(int m){ return rev3c(m>>5) + 8*rev5(m&31); }
// x-axis frequency permutation at PHYSICAL float2 index q (float4-packed storage)
__device__ __forceinline__ int sigx(int q){ return rev3c(2*(q>>6) + (q&1)) + 8*rev5((q>>1)&31); }

__device__ __forceinline__ float2 shflx(float2 v, int d){
    v.x = __shfl_xor_sync(0xffffffffu, v.x, d);
    v.y = __shfl_xor_sync(0xffffffffu, v.y, d);
    return v;
}

// ---------------- per-lane FFT constants ----------------
struct WF { float2 w16, w8, w4, w2, base; float t16, t8, t4, t2, t1; };
__device__ __forceinline__ WF make_wf(int l){
    WF W; float s, c;
    __sincosf(-(TWO_PI/256.0f)*(float)l, &s, &c); W.base = make_float2(c, s);
    __sincosf(-(PI_F/16.0f)*(float)(l&15), &s, &c); W.w16 = (l&16)? make_float2(c,s) : make_float2(1.f,0.f);
    __sincosf(-(PI_F/ 8.0f)*(float)(l& 7), &s, &c); W.w8  = (l& 8)? make_float2(c,s) : make_float2(1.f,0.f);
    __sincosf(-(PI_F/ 4.0f)*(float)(l& 3), &s, &c); W.w4  = (l& 4)? make_float2(c,s) : make_float2(1.f,0.f);
    __sincosf(-(PI_F/ 2.0f)*(float)(l& 1), &s, &c); W.w2  = (l& 2)? make_float2(c,s) : make_float2(1.f,0.f);
    W.t16 = (l&16)? -1.f:1.f;  W.t8 = (l&8)? -1.f:1.f;  W.t4 = (l&4)? -1.f:1.f;
    W.t2  = (l& 2)? -1.f:1.f;  W.t1 = (l&1)? -1.f:1.f;
    return W;
}

#define RC8 0.70710678118654752440f

// DIF-8 in registers: natural in, bitrev3 out
__device__ __forceinline__ void fft8(float2 v[8]){
    float2 t0=cadd(v[0],v[4]), t1=cadd(v[1],v[5]), t2=cadd(v[2],v[6]), t3=cadd(v[3],v[7]);
    float2 u0=csub(v[0],v[4]);
    float2 d1=csub(v[1],v[5]); float2 u1=make_float2(RC8*(d1.x+d1.y), RC8*(d1.y-d1.x));
    float2 d2=csub(v[2],v[6]); float2 u2=make_float2(d2.y, -d2.x);
    float2 d3=csub(v[3],v[7]); float2 u3=make_float2(RC8*(d3.y-d3.x), -RC8*(d3.x+d3.y));
    float2 a0=cadd(t0,t2), a1=cadd(t1,t3), a2=csub(t0,t2);
    float2 dt=csub(t1,t3); float2 a3=make_float2(dt.y,-dt.x);
    float2 b0=cadd(u0,u2), b1=cadd(u1,u3), b2=csub(u0,u2);
    float2 du=csub(u1,u3); float2 b3=make_float2(du.y,-du.x);
    v[0]=cadd(a0,a1); v[1]=csub(a0,a1); v[2]=cadd(a2,a3); v[3]=csub(a2,a3);
    v[4]=cadd(b0,b1); v[5]=csub(b0,b1); v[6]=cadd(b2,b3); v[7]=csub(b2,b3);
}

// DIT-8 in registers: bitrev3 in, natural out, e^{+}
__device__ __forceinline__ void ifft8(float2 v[8]){
    float2 s0=cadd(v[0],v[1]), d0=csub(v[0],v[1]);
    float2 s1=cadd(v[2],v[3]), d1=csub(v[2],v[3]);
    float2 s2=cadd(v[4],v[5]), d2=csub(v[4],v[5]);
    float2 s3=cadd(v[6],v[7]), d3=csub(v[6],v[7]);
    float2 id1=make_float2(-d1.y,d1.x), id3=make_float2(-d3.y,d3.x);
    float2 p0=cadd(s0,s1), p2=csub(s0,s1), p1=cadd(d0,id1), p3=csub(d0,id1);
    float2 q0=cadd(s2,s3), q2=csub(s2,s3), q1=cadd(d2,id3), q3=csub(d2,id3);
    float2 w1q=make_float2(RC8*(q1.x-q1.y), RC8*(q1.x+q1.y));
    float2 iq2=make_float2(-q2.y,q2.x);
    float2 w3q=make_float2(-RC8*(q3.x+q3.y), RC8*(q3.x-q3.y));
    v[0]=cadd(p0,q0);  v[4]=csub(p0,q0);
    v[1]=cadd(p1,w1q); v[5]=csub(p1,w1q);
    v[2]=cadd(p2,iq2); v[6]=csub(p2,iq2);
    v[3]=cadd(p3,w3q); v[7]=csub(p3,w3q);
}

__device__ __forceinline__ void twchain(float2 v[8], float2 base){
    float2 w = base;
    v[4]=cmul(v[4],w); w=cmul(w,base);
    v[2]=cmul(v[2],w); w=cmul(w,base);
    v[6]=cmul(v[6],w); w=cmul(w,base);
    v[1]=cmul(v[1],w); w=cmul(w,base);
    v[5]=cmul(v[5],w); w=cmul(w,base);
    v[3]=cmul(v[3],w); w=cmul(w,base);
    v[7]=cmul(v[7],w);
}

// ---- select-free cross-lane stages (packed butterfly combine) ----
__device__ __forceinline__ void fstage(float2 v[8], int D, float2 w, float t){
    #pragma unroll
    for (int k = 0; k < 8; k++){
        float2 p = shflx(v[k], D);
        float2 u = cfma1(t, v[k], p);
        v[k] = cmul(w, u);
    }
}
__device__ __forceinline__ void fstage1(float2 v[8], float t){
    #pragma unroll
    for (int k = 0; k < 8; k++){
        float2 p = shflx(v[k], 1);
        v[k] = cfma1(t, v[k], p);
    }
}
__device__ __forceinline__ void istage(float2 v[8], int D, float2 w, float t){
    #pragma unroll
    for (int k = 0; k < 8; k++){
        float2 y = cmulc(w, v[k]);
        float2 p = shflx(y, D);
        v[k] = cfma1(t, y, p);
    }
}
__device__ __forceinline__ void istage1(float2 v[8], float t){
    #pragma unroll
    for (int k = 0; k < 8; k++){
        float2 p = shflx(v[k], 1);
        v[k] = cfma1(t, v[k], p);
    }
}

__device__ __forceinline__ void fwd256(float2 v[8], const WF& W){
    fft8(v);
    twchain(v, W.base);
    fstage(v,16,W.w16,W.t16);
    fstage(v, 8,W.w8 ,W.t8 );
    fstage(v, 4,W.w4 ,W.t4 );
    fstage(v, 2,W.w2 ,W.t2 );
    fstage1(v, W.t1);
}
__device__ __forceinline__ void inv256(float2 v[8], const WF& W){
    istage1(v, W.t1);
    istage(v, 2,W.w2 ,W.t2 );
    istage(v, 4,W.w4 ,W.t4 );
    istage(v, 8,W.w8 ,W.t8 );
    istage(v,16,W.w16,W.t16);
    twchain(v, conjf2(W.base));
    ifft8(v);
}

// ---- float4-packed row I/O ----
__device__ __forceinline__ void load8(float2 v[8], const float2* row, int l){
    const float4* r4 = (const float4*)row;
    #pragma unroll
    for (int rp = 0; rp < 4; rp++){
        float4 q = r4[l + 32*rp];
        v[2*rp]   = make_float2(q.x, q.y);
        v[2*rp+1] = make_float2(q.z, q.w);
    }
}
__device__ __forceinline__ void store8(float2* row, const float2 v[8], int l){
    float4* r4 = (float4*)row;
    #pragma unroll
    for (int rp = 0; rp < 4; rp++)
        r4[l + 32*rp] = make_float4(v[2*rp].x, v[2*rp].y, v[2*rp+1].x, v[2*rp+1].y);
}

// ---------------- setup (merged: H permute + index resolution) ----------------
__global__ void k_setup_H(const float* __restrict__ Hr, const float* __restrict__ Hi,
                          const float* __restrict__ shifts,
                          const int*   __restrict__ crop,
                          const void*  __restrict__ idxraw){
    int idx = blockIdx.x*256 + threadIdx.x;
    int my = idx & 255, mx = idx >> 8;
    int ky = sigma(my), kx = sigx(mx);
    size_t hsrc = (size_t)ky*N_ + kx;
    g_Ht[(size_t)mx*N_ + my] = make_float2(Hr[hsrc]*(1.0f/256.0f), Hi[hsrc]*(1.0f/256.0f));
    if (idx == 0){
        const int* w = (const int*)idxraw;
        int orr = 0;
        for (int k = 1; k < NB_; k += 2) orr |= w[k];
        bool is64 = (orr == 0);
        for (int b = 0; b < NB_; b++){
            int id = is64 ? (int)(((const long long*)idxraw)[b]) : w[b];
            g_cy[b] = crop[2*id];
            g_cx[b] = crop[2*id + 1];
            g_sy[b] = shifts[2*id];
            g_sx[b] = shifts[2*id + 1];
        }
    }
}

// ---------------- probe fft2 ----------------
__global__ void k_probe_rows(const float* __restrict__ pr, const float* __restrict__ pi){
    int blk = blockIdx.x, rb = blk & 31, p = blk >> 5;
    int w = threadIdx.x >> 5, l = threadIdx.x & 31;
    int y = rb*8 + w;
    WF W = make_wf(l);
    size_t base = ((size_t)p*N_ + y)*N_;
    float2 v[8];
    #pragma unroll
    for (int r = 0; r < 8; r++){ int x = l + 32*r; v[r] = make_float2(pr[base+x], pi[base+x]); }
    fwd256(v, W);
    store8(g_probeF + base, v, l);
}

__global__ void k_probe_cols(){
    __shared__ float2 tile[2048];
    int blk = blockIdx.x, t = blk & 31, p = blk >> 5;
    int xg0 = t*8;
    int w = threadIdx.x >> 5, l = threadIdx.x & 31;
    WF W = make_wf(l);
    float2* F = g_probeF + (size_t)p*NF;
    #pragma unroll
    for (int c = 0; c < 8; c++){
        int e = threadIdx.x + 256*c; int j = e & 7, my = e >> 3;
        tile[TADDR(my,j)] = F[(size_t)my*N_ + xg0 + j];
    }
    __syncthreads();
    float2 v[8];
    #pragma unroll
    for (int r = 0; r < 8; r++) v[r] = tile[TADDR(l+32*r, w)];
    fwd256(v, W);
    #pragma unroll
    for (int r = 0; r < 8; r++) tile[TADDR(l+32*r, w)] = v[r];
    __syncthreads();
    #pragma unroll
    for (int c = 0; c < 8; c++){
        int e = threadIdx.x + 256*c; int j = e & 7, my = e >> 3;
        F[(size_t)my*N_ + xg0 + j] = tile[TADDR(my,j)];
    }
}

// ---------------- shifted probes ----------------
__global__ void k_probes_rows(){
    int blk = blockIdx.x, rb = blk & 31, bp = blk >> 5;
    int p = bp & 7, b = bp >> 3;
    int w = threadIdx.x >> 5, l = threadIdx.x & 31;
    int my = rb*8 + w;
    WF W = make_wf(l);
    float sy = g_sy[b], sx = g_sx[b];
    int ky = sigma(my);
    float f = sy*(float)ky*(1.0f/256.0f) + sx*(float)rev5(l)*(1.0f/32.0f);
    f -= rintf(f);
    float s, c; __sincosf(-TWO_PI*f, &s, &c);
    float2 C = make_float2(c*(1.0f/256.0f), s*(1.0f/256.0f));
    float fb = sx*(1.0f/256.0f); fb -= rintf(fb);
    __sincosf(-TWO_PI*fb, &s, &c); float2 B = make_float2(c, s);
    size_t base = ((size_t)p*N_ + my)*N_;
    float2 v[8];
    load8(v, g_probeF + base, l);
    float2 wv = C;
    v[0]=cmul(v[0],wv); wv=cmul(wv,B);
    v[4]=cmul(v[4],wv); wv=cmul(wv,B);
    v[2]=cmul(v[2],wv); wv=cmul(wv,B);
    v[6]=cmul(v[6],wv); wv=cmul(wv,B);
    v[1]=cmul(v[1],wv); wv=cmul(wv,B);
    v[5]=cmul(v[5],wv); wv=cmul(wv,B);
    v[3]=cmul(v[3],wv); wv=cmul(wv,B);
    v[7]=cmul(v[7],wv);
    inv256(v, W);
    store8(g_probes + ((size_t)b*P_ + p)*NF + (size_t)my*N_, v, l);
}

__global__ void k_probes_cols(){
    __shared__ float2 tile[2048];
    int blk = blockIdx.x, t = blk & 31, f = blk >> 5;
    int xg0 = t*8;
    int w = threadIdx.x >> 5, l = threadIdx.x & 31;
    WF W = make_wf(l);
    float2* F = g_probes + (size_t)f*NF;
    #pragma unroll
    for (int c = 0; c < 8; c++){
        int e = threadIdx.x + 256*c; int j = e & 7, my = e >> 3;
        tile[TADDR(my,j)] = F[(size_t)my*N_ + xg0 + j];
    }
    __syncthreads();
    float2 v[8];
    #pragma unroll
    for (int r = 0; r < 8; r++) v[r] = tile[TADDR(l+32*r, w)];
    inv256(v, W);
    #pragma unroll
    for (int r = 0; r < 8; r++){
        v[r].x *= (1.0f/256.0f); v[r].y *= (1.0f/256.0f);
        tile[TADDR(l+32*r, w)] = v[r];
    }
    __syncthreads();
    #pragma unroll
    for (int c = 0; c < 8; c++){
        int e = threadIdx.x + 256*c; int j = e & 7, my = e >> 3;
        F[(size_t)my*N_ + xg0 + j] = tile[TADDR(my,j)];
    }
}

// ---------------- rows pass A (software-pipelined p-loop) ----------------
__global__ void k_rows_A(const float* __restrict__ obja, const float* __restrict__ objp,
                         float* __restrict__ pp_out, int z){
    int blk = blockIdx.x, rb = blk & 31, bo = blk >> 5;
    int o = bo & 1, b = bo >> 1;
    int w = threadIdx.x >> 5, l = threadIdx.x & 31;
    int y = rb*8 + w;
    WF W = make_wf(l);
    int cy = g_cy[b], cx = g_cx[b];
    size_t obase = ((size_t)(o*Z_ + z)*OY_ + (size_t)(cy + y))*OY_ + cx;
    float scale = (z == 0) ? 1.0f : (1.0f/256.0f);
    size_t ppbase = ((((size_t)b*O_ + o)*Z_ + z)*N_ + y)*(size_t)N_;
    float2 obj[8];
    #pragma unroll
    for (int r = 0; r < 8; r++){
        int x = l + 32*r;
        float A = obja[obase + x], ph = objp[obase + x];
        float sn, cs; __sincosf(ph, &sn, &cs);
        obj[r] = make_float2(A*cs*scale, A*sn*scale);
        pp_out[ppbase + x] = ph;
    }
    const float2* srcbase = (z == 0)
        ? g_probes + (size_t)b*P_*NF + (size_t)y*N_
        : g_bufB  + (size_t)bo*P_*NF + (size_t)y*N_;
    float2* dstbase = g_bufA + (size_t)bo*P_*NF + (size_t)y*N_;

    float2 vn[8];
    load8(vn, srcbase, l);                      // prefetch p=0
    #pragma unroll
    for (int p = 0; p < P_; p++){
        float2 v[8];
        #pragma unroll
        for (int r = 0; r < 8; r++) v[r] = vn[r];
        if (p < P_-1) load8(vn, srcbase + (size_t)(p+1)*NF, l);   // prefetch next field
        if (z) inv256(v, W);
        #pragma unroll
        for (int r = 0; r < 8; r++) v[r] = cmul(v[r], obj[r]);
        fwd256(v, W);
        store8(dstbase + (size_t)p*NF, v, l);
    }
}

// ---------------- cols pass B ----------------
__global__ void k_cols_H(){
    __shared__ float2 tile[2048];
    int blk = blockIdx.x, t = blk & 31, f = blk >> 5;
    int xg0 = t*8;
    int w = threadIdx.x >> 5, l = threadIdx.x & 31;
    WF W = make_wf(l);
    const float2* s = g_bufA + (size_t)f*NF;
    #pragma unroll
    for (int c = 0; c < 8; c++){
        int e = threadIdx.x + 256*c; int j = e & 7, my = e >> 3;
        tile[TADDR(my,j)] = s[(size_t)my*N_ + xg0 + j];
    }
    __syncthreads();
    float2 v[8];
    #pragma unroll
    for (int r = 0; r < 8; r++) v[r] = tile[TADDR(l+32*r, w)];
    fwd256(v, W);
    const float2* Hc = g_Ht + (size_t)(xg0 + w)*N_;
    #pragma unroll
    for (int r = 0; r < 8; r++) v[r] = cmul(v[r], Hc[l + 32*r]);
    inv256(v, W);
    #pragma unroll
    for (int r = 0; r < 8; r++) tile[TADDR(l+32*r, w)] = v[r];
    __syncthreads();
    float2* d = g_bufB + (size_t)f*NF;
    #pragma unroll
    for (int c = 0; c < 8; c++){
        int e = threadIdx.x + 256*c; int j = e & 7, my = e >> 3;
        d[(size_t)my*N_ + xg0 + j] = tile[TADDR(my,j)];
    }
}

// ---------------- final ----------------
__global__ void k_cols_final(const float* __restrict__ occu, float* __restrict__ dp){
    __shared__ float2 tile[2048];
    int blk = blockIdx.x, t = blk & 31, b = blk >> 5;
    int xg0 = t*8;
    int w = threadIdx.x >> 5, l = threadIdx.x & 31;
    WF W = make_wf(l);
    float acc[8];
    #pragma unroll
    for (int k = 0; k < 8; k++) acc[k] = 0.0f;
    for (int o = 0; o < O_; o++){
        float wt = occu[o];
        for (int p = 0; p < P_; p++){
            const float2* s = g_bufA + ((size_t)((b*O_ + o)*P_ + p))*NF;
            __syncthreads();
            #pragma unroll
            for (int c = 0; c < 8; c++){
                int e = threadIdx.x + 256*c; int j = e & 7, my = e >> 3;
                tile[TADDR(my,j)] = s[(size_t)my*N_ + xg0 + j];
            }
            __syncthreads();
            float2 v[8];
            #pragma unroll
            for (int r = 0; r < 8; r++) v[r] = tile[TADDR(l+32*r, w)];
            fwd256(v, W);
            #pragma unroll
            for (int r = 0; r < 8; r++) acc[r] += wt*(v[r].x*v[r].x + v[r].y*v[r].y);
        }
    }
    int kx = sigx(xg0 + w);
    int xs = (kx + 128) & 255;
    int r5 = rev5(l);
    #pragma unroll
    for (int r = 0; r < 8; r++){
        int ky = rev3c(r) + 8*r5;
        dp[(size_t)b*NF + (size_t)((ky + 128) & 255)*N_ + xs] = acc[r];
    }
}

// ---------------- launch ----------------
extern "C" void kernel_launch(void* const* d_in, const int* in_sizes, int n_in,
                              void* d_out, int out_size){
    const float* obja   = (const float*)d_in[0];
    const float* objp   = (const float*)d_in[1];
    const float* pr     = (const float*)d_in[2];
    const float* pi     = (const float*)d_in[3];
    const float* Hr     = (const float*)d_in[4];
    const float* Hi     = (const float*)d_in[5];
    const float* occu   = (const float*)d_in[6];
    const float* shifts = (const float*)d_in[7];
    const int*   crop   = (const int*)d_in[8];
    const void*  idx    = d_in[9];

    float* dp = (float*)d_out;                    // (NB, 256, 256)
    float* pp = dp + (size_t)NB_ * NF;            // (NB, O, Z, 256, 256)

    k_setup_H<<<256, 256>>>(Hr, Hi, shifts, crop, idx);
    k_probe_rows<<<P_*32, 256>>>(pr, pi);
    k_probe_cols<<<P_*32, 256>>>();
    k_probes_rows<<<NB_*P_*32, 256>>>();
    k_probes_cols<<<NB_*P_*32, 256>>>();

    k_rows_A<<<NB_*O_*32, 256>>>(obja, objp, pp, 0);
    for (int z = 0; z < Z_ - 1; z++){
        k_cols_H<<<NB_*O_*P_*32, 256>>>();
        k_rows_A<<<NB_*O_*32, 256>>>(obja, objp, pp, z + 1);
    }
    k_cols_final<<<NB_*32, 256>>>(occu, dp);
}

// round 12
// speedup vs baseline: 1.3247x; 1.0649x over previous
#include <cuda_runtime.h>

// ---------------- problem constants ----------------
#define O_    2
#define Z_    8
#define OY_   1024
#define P_    8
#define N_    256
#define NB_   32
#define NF    65536
#define TWO_PI 6.28318530717958647692f
#define PI_F  3.14159265358979323846f

// XOR-swizzled column-tile addressing, 8 cols (float2)
#define TADDR(my,j)   ((((my) << 3)) | ((j) ^ (((my) >> 2) & 7)))
// 16-col variant: conflict-free for 128B-row staging AND per-warp column reads
// (addr mod 16 = j ^ (my&15): staging has my const per 16-lane group -> 16 residues;
//  column reads have j const -> l&15 spans 16 residues)
#define TADDR16(my,j) ((((my) << 4)) | ((j) ^ ((my) & 15)))

// ---------------- static device scratch ----------------
__device__ int    g_cy[NB_], g_cx[NB_];
__device__ float  g_sy[NB_], g_sx[NB_];
__device__ float2 g_Ht[(size_t)NF];                                   // H permuted both axes, /256 folded
__device__ __align__(16) float2 g_probeF[(size_t)P_ * NF];
__device__ __align__(16) float2 g_probes[(size_t)NB_ * P_ * NF];
__device__ __align__(16) float2 g_bufA[(size_t)NB_ * O_ * P_ * NF];
__device__ __align__(16) float2 g_bufB[(size_t)NB_ * O_ * P_ * NF];

// ---------------- packed f32x2 complex helpers ----------------
__device__ __forceinline__ float2 cadd(float2 a, float2 b){
    float2 r;
    asm("{\n\t.reg .b64 ra, rb, rr;\n\t"
        "mov.b64 ra, {%2,%3};\n\t"
        "mov.b64 rb, {%4,%5};\n\t"
        "add.rn.f32x2 rr, ra, rb;\n\t"
        "mov.b64 {%0,%1}, rr;\n\t}"
        : "=f"(r.x), "=f"(r.y) : "f"(a.x), "f"(a.y), "f"(b.x), "f"(b.y));
    return r;
}
__device__ __forceinline__ float2 csub(float2 a, float2 b){
    float2 r;
    asm("{\n\t.reg .b64 ra, rb, rn, rr;\n\t"
        "mov.b64 ra, {%2,%3};\n\t"
        "mov.b64 rb, {%4,%5};\n\t"
        "mov.b64 rn, 0xBF800000BF800000;\n\t"
        "fma.rn.f32x2 rr, rb, rn, ra;\n\t"
        "mov.b64 {%0,%1}, rr;\n\t}"
        : "=f"(r.x), "=f"(r.y) : "f"(a.x), "f"(a.y), "f"(b.x), "f"(b.y));
    return r;
}
__device__ __forceinline__ float2 cfma1(float t, float2 v, float2 p){
    float2 r;
    asm("{\n\t.reg .b64 rv, rp, rt, rr;\n\t"
        "mov.b64 rv, {%3,%4};\n\t"
        "mov.b64 rp, {%5,%6};\n\t"
        "mov.b64 rt, {%2,%2};\n\t"
        "fma.rn.f32x2 rr, rv, rt, rp;\n\t"
        "mov.b64 {%0,%1}, rr;\n\t}"
        : "=f"(r.x), "=f"(r.y) : "f"(t), "f"(v.x), "f"(v.y), "f"(p.x), "f"(p.y));
    return r;
}
__device__ __forceinline__ float2 cmul(float2 a, float2 b){ return make_float2(a.x*b.x - a.y*b.y, a.x*b.y + a.y*b.x); }
__device__ __forceinline__ float2 cmulc(float2 t, float2 x){ return make_float2(t.x*x.x + t.y*x.y, t.x*x.y - t.y*x.x); }
__device__ __forceinline__ float2 conjf2(float2 a){ return make_float2(a.x, -a.y); }

__device__ __forceinline__ int rev5(int l){ return (int)(__brev((unsigned)l) >> 27); }
__device__ __forceinline__ int rev3c(int r){ return ((r&1)<<2) | (r&2) | ((r&4)>>2); }
__device__ __forceinline__ int sigma(int m){ return rev3c(m>>5) + 8*rev5(m&31); }
__device__ __forceinline__ int sigx(int q){ return rev3c(2*(q>>6) + (q&1)) + 8*rev5((q>>1)&31); }

__device__ __forceinline__ float2 shflx(float2 v, int d){
    v.x = __shfl_xor_sync(0xffffffffu, v.x, d);
    v.y = __shfl_xor_sync(0xffffffffu, v.y, d);
    return v;
}

// ---------------- per-lane FFT constants ----------------
struct WF { float2 w16, w8, w4, w2, base; float t16, t8, t4, t2, t1; };
__device__ __forceinline__ WF make_wf(int l){
    WF W; float s, c;
    __sincosf(-(TWO_PI/256.0f)*(float)l, &s, &c); W.base = make_float2(c, s);
    __sincosf(-(PI_F/16.0f)*(float)(l&15), &s, &c); W.w16 = (l&16)? make_float2(c,s) : make_float2(1.f,0.f);
    __sincosf(-(PI_F/ 8.0f)*(float)(l& 7), &s, &c); W.w8  = (l& 8)? make_float2(c,s) : make_float2(1.f,0.f);
    __sincosf(-(PI_F/ 4.0f)*(float)(l& 3), &s, &c); W.w4  = (l& 4)? make_float2(c,s) : make_float2(1.f,0.f);
    __sincosf(-(PI_F/ 2.0f)*(float)(l& 1), &s, &c); W.w2  = (l& 2)? make_float2(c,s) : make_float2(1.f,0.f);
    W.t16 = (l&16)? -1.f:1.f;  W.t8 = (l&8)? -1.f:1.f;  W.t4 = (l&4)? -1.f:1.f;
    W.t2  = (l& 2)? -1.f:1.f;  W.t1 = (l&1)? -1.f:1.f;
    return W;
}

#define RC8 0.70710678118654752440f

// DIF-8 in registers: natural in, bitrev3 out
__device__ __forceinline__ void fft8(float2 v[8]){
    float2 t0=cadd(v[0],v[4]), t1=cadd(v[1],v[5]), t2=cadd(v[2],v[6]), t3=cadd(v[3],v[7]);
    float2 u0=csub(v[0],v[4]);
    float2 d1=csub(v[1],v[5]); float2 u1=make_float2(RC8*(d1.x+d1.y), RC8*(d1.y-d1.x));
    float2 d2=csub(v[2],v[6]); float2 u2=make_float2(d2.y, -d2.x);
    float2 d3=csub(v[3],v[7]); float2 u3=make_float2(RC8*(d3.y-d3.x), -RC8*(d3.x+d3.y));
    float2 a0=cadd(t0,t2), a1=cadd(t1,t3), a2=csub(t0,t2);
    float2 dt=csub(t1,t3); float2 a3=make_float2(dt.y,-dt.x);
    float2 b0=cadd(u0,u2), b1=cadd(u1,u3), b2=csub(u0,u2);
    float2 du=csub(u1,u3); float2 b3=make_float2(du.y,-du.x);
    v[0]=cadd(a0,a1); v[1]=csub(a0,a1); v[2]=cadd(a2,a3); v[3]=csub(a2,a3);
    v[4]=cadd(b0,b1); v[5]=csub(b0,b1); v[6]=cadd(b2,b3); v[7]=csub(b2,b3);
}

// DIT-8 in registers: bitrev3 in, natural out, e^{+}
__device__ __forceinline__ void ifft8(float2 v[8]){
    float2 s0=cadd(v[0],v[1]), d0=csub(v[0],v[1]);
    float2 s1=cadd(v[2],v[3]), d1=csub(v[2],v[3]);
    float2 s2=cadd(v[4],v[5]), d2=csub(v[4],v[5]);
    float2 s3=cadd(v[6],v[7]), d3=csub(v[6],v[7]);
    float2 id1=make_float2(-d1.y,d1.x), id3=make_float2(-d3.y,d3.x);
    float2 p0=cadd(s0,s1), p2=csub(s0,s1), p1=cadd(d0,id1), p3=csub(d0,id1);
    float2 q0=cadd(s2,s3), q2=csub(s2,s3), q1=cadd(d2,id3), q3=csub(d2,id3);
    float2 w1q=make_float2(RC8*(q1.x-q1.y), RC8*(q1.x+q1.y));
    float2 iq2=make_float2(-q2.y,q2.x);
    float2 w3q=make_float2(-RC8*(q3.x+q3.y), RC8*(q3.x-q3.y));
    v[0]=cadd(p0,q0);  v[4]=csub(p0,q0);
    v[1]=cadd(p1,w1q); v[5]=csub(p1,w1q);
    v[2]=cadd(p2,iq2); v[6]=csub(p2,iq2);
    v[3]=cadd(p3,w3q); v[7]=csub(p3,w3q);
}

__device__ __forceinline__ void twchain(float2 v[8], float2 base){
    float2 w = base;
    v[4]=cmul(v[4],w); w=cmul(w,base);
    v[2]=cmul(v[2],w); w=cmul(w,base);
    v[6]=cmul(v[6],w); w=cmul(w,base);
    v[1]=cmul(v[1],w); w=cmul(w,base);
    v[5]=cmul(v[5],w); w=cmul(w,base);
    v[3]=cmul(v[3],w); w=cmul(w,base);
    v[7]=cmul(v[7],w);
}

// ---- single-chain cross-lane stages ----
__device__ __forceinline__ void fstage(float2 v[8], int D, float2 w, float t){
    #pragma unroll
    for (int k = 0; k < 8; k++){
        float2 p = shflx(v[k], D);
        v[k] = cmul(w, cfma1(t, v[k], p));
    }
}
__device__ __forceinline__ void fstage1(float2 v[8], float t){
    #pragma unroll
    for (int k = 0; k < 8; k++){
        float2 p = shflx(v[k], 1);
        v[k] = cfma1(t, v[k], p);
    }
}
__device__ __forceinline__ void istage(float2 v[8], int D, float2 w, float t){
    #pragma unroll
    for (int k = 0; k < 8; k++){
        float2 y = cmulc(w, v[k]);
        float2 p = shflx(y, D);
        v[k] = cfma1(t, y, p);
    }
}
__device__ __forceinline__ void istage1(float2 v[8], float t){
    #pragma unroll
    for (int k = 0; k < 8; k++){
        float2 p = shflx(v[k], 1);
        v[k] = cfma1(t, v[k], p);
    }
}

__device__ __forceinline__ void fwd256(float2 v[8], const WF& W){
    fft8(v);
    twchain(v, W.base);
    fstage(v,16,W.w16,W.t16);
    fstage(v, 8,W.w8 ,W.t8 );
    fstage(v, 4,W.w4 ,W.t4 );
    fstage(v, 2,W.w2 ,W.t2 );
    fstage1(v, W.t1);
}
__device__ __forceinline__ void inv256(float2 v[8], const WF& W){
    istage1(v, W.t1);
    istage(v, 2,W.w2 ,W.t2 );
    istage(v, 4,W.w4 ,W.t4 );
    istage(v, 8,W.w8 ,W.t8 );
    istage(v,16,W.w16,W.t16);
    twchain(v, conjf2(W.base));
    ifft8(v);
}

// ---- paired (ILP2) stages: two independent chains interleaved ----
__device__ __forceinline__ void fstage2(float2 a[8], float2 b[8], int D, float2 w, float t){
    #pragma unroll
    for (int k = 0; k < 8; k++){
        float2 pa = shflx(a[k], D);
        float2 pb = shflx(b[k], D);
        a[k] = cmul(w, cfma1(t, a[k], pa));
        b[k] = cmul(w, cfma1(t, b[k], pb));
    }
}
__device__ __forceinline__ void fstage1_2(float2 a[8], float2 b[8], float t){
    #pragma unroll
    for (int k = 0; k < 8; k++){
        float2 pa = shflx(a[k], 1);
        float2 pb = shflx(b[k], 1);
        a[k] = cfma1(t, a[k], pa);
        b[k] = cfma1(t, b[k], pb);
    }
}
__device__ __forceinline__ void istage2(float2 a[8], float2 b[8], int D, float2 w, float t){
    #pragma unroll
    for (int k = 0; k < 8; k++){
        float2 ya = cmulc(w, a[k]);
        float2 yb = cmulc(w, b[k]);
        float2 pa = shflx(ya, D);
        float2 pb = shflx(yb, D);
        a[k] = cfma1(t, ya, pa);
        b[k] = cfma1(t, yb, pb);
    }
}
__device__ __forceinline__ void istage1_2(float2 a[8], float2 b[8], float t){
    #pragma unroll
    for (int k = 0; k < 8; k++){
        float2 pa = shflx(a[k], 1);
        float2 pb = shflx(b[k], 1);
        a[k] = cfma1(t, a[k], pa);
        b[k] = cfma1(t, b[k], pb);
    }
}
__device__ __forceinline__ void fwd256_2(float2 a[8], float2 b[8], const WF& W){
    fft8(a); fft8(b);
    twchain(a, W.base); twchain(b, W.base);
    fstage2(a,b,16,W.w16,W.t16);
    fstage2(a,b, 8,W.w8 ,W.t8 );
    fstage2(a,b, 4,W.w4 ,W.t4 );
    fstage2(a,b, 2,W.w2 ,W.t2 );
    fstage1_2(a,b, W.t1);
}
__device__ __forceinline__ void inv256_2(float2 a[8], float2 b[8], const WF& W){
    istage1_2(a,b, W.t1);
    istage2(a,b, 2,W.w2 ,W.t2 );
    istage2(a,b, 4,W.w4 ,W.t4 );
    istage2(a,b, 8,W.w8 ,W.t8 );
    istage2(a,b,16,W.w16,W.t16);
    float2 cb = conjf2(W.base);
    twchain(a, cb); twchain(b, cb);
    ifft8(a); ifft8(b);
}

// ---- float4-packed row I/O ----
__device__ __forceinline__ void load8(float2 v[8], const float2* row, int l){
    const float4* r4 = (const float4*)row;
    #pragma unroll
    for (int rp = 0; rp < 4; rp++){
        float4 q = r4[l + 32*rp];
        v[2*rp]   = make_float2(q.x, q.y);
        v[2*rp+1] = make_float2(q.z, q.w);
    }
}
__device__ __forceinline__ void store8(float2* row, const float2 v[8], int l){
    float4* r4 = (float4*)row;
    #pragma unroll
    for (int rp = 0; rp < 4; rp++)
        r4[l + 32*rp] = make_float4(v[2*rp].x, v[2*rp].y, v[2*rp+1].x, v[2*rp+1].y);
}

// ---------------- setup ----------------
__global__ void k_setup_H(const float* __restrict__ Hr, const float* __restrict__ Hi,
                          const float* __restrict__ shifts,
                          const int*   __restrict__ crop,
                          const void*  __restrict__ idxraw){
    int idx = blockIdx.x*256 + threadIdx.x;
    int my = idx & 255, mx = idx >> 8;
    int ky = sigma(my), kx = sigx(mx);
    size_t hsrc = (size_t)ky*N_ + kx;
    g_Ht[(size_t)mx*N_ + my] = make_float2(Hr[hsrc]*(1.0f/256.0f), Hi[hsrc]*(1.0f/256.0f));
    if (idx == 0){
        const int* w = (const int*)idxraw;
        int orr = 0;
        for (int k = 1; k < NB_; k += 2) orr |= w[k];
        bool is64 = (orr == 0);
        for (int b = 0; b < NB_; b++){
            int id = is64 ? (int)(((const long long*)idxraw)[b]) : w[b];
            g_cy[b] = crop[2*id];
            g_cx[b] = crop[2*id + 1];
            g_sy[b] = shifts[2*id];
            g_sx[b] = shifts[2*id + 1];
        }
    }
}

// ---------------- probe fft2 ----------------
__global__ void k_probe_rows(const float* __restrict__ pr, const float* __restrict__ pi){
    int blk = blockIdx.x, rb = blk & 31, p = blk >> 5;
    int w = threadIdx.x >> 5, l = threadIdx.x & 31;
    int y = rb*8 + w;
    WF W = make_wf(l);
    size_t base = ((size_t)p*N_ + y)*N_;
    float2 v[8];
    #pragma unroll
    for (int r = 0; r < 8; r++){ int x = l + 32*r; v[r] = make_float2(pr[base+x], pi[base+x]); }
    fwd256(v, W);
    store8(g_probeF + base, v, l);
}

__global__ void k_probe_cols(){
    __shared__ float2 tile[2048];
    int blk = blockIdx.x, t = blk & 31, p = blk >> 5;
    int xg0 = t*8;
    int w = threadIdx.x >> 5, l = threadIdx.x & 31;
    WF W = make_wf(l);
    float2* F = g_probeF + (size_t)p*NF;
    #pragma unroll
    for (int c = 0; c < 8; c++){
        int e = threadIdx.x + 256*c; int j = e & 7, my = e >> 3;
        tile[TADDR(my,j)] = F[(size_t)my*N_ + xg0 + j];
    }
    __syncthreads();
    float2 v[8];
    #pragma unroll
    for (int r = 0; r < 8; r++) v[r] = tile[TADDR(l+32*r, w)];
    fwd256(v, W);
    #pragma unroll
    for (int r = 0; r < 8; r++) tile[TADDR(l+32*r, w)] = v[r];
    __syncthreads();
    #pragma unroll
    for (int c = 0; c < 8; c++){
        int e = threadIdx.x + 256*c; int j = e & 7, my = e >> 3;
        F[(size_t)my*N_ + xg0 + j] = tile[TADDR(my,j)];
    }
}

// ---------------- shifted probes ----------------
__global__ void k_probes_rows(){
    int blk = blockIdx.x, rb = blk & 31, bp = blk >> 5;
    int p = bp & 7, b = bp >> 3;
    int w = threadIdx.x >> 5, l = threadIdx.x & 31;
    int my = rb*8 + w;
    WF W = make_wf(l);
    float sy = g_sy[b], sx = g_sx[b];
    int ky = sigma(my);
    float f = sy*(float)ky*(1.0f/256.0f) + sx*(float)rev5(l)*(1.0f/32.0f);
    f -= rintf(f);
    float s, c; __sincosf(-TWO_PI*f, &s, &c);
    float2 C = make_float2(c*(1.0f/256.0f), s*(1.0f/256.0f));
    float fb = sx*(1.0f/256.0f); fb -= rintf(fb);
    __sincosf(-TWO_PI*fb, &s, &c); float2 B = make_float2(c, s);
    size_t base = ((size_t)p*N_ + my)*N_;
    float2 v[8];
    load8(v, g_probeF + base, l);
    float2 wv = C;
    v[0]=cmul(v[0],wv); wv=cmul(wv,B);
    v[4]=cmul(v[4],wv); wv=cmul(wv,B);
    v[2]=cmul(v[2],wv); wv=cmul(wv,B);
    v[6]=cmul(v[6],wv); wv=cmul(wv,B);
    v[1]=cmul(v[1],wv); wv=cmul(wv,B);
    v[5]=cmul(v[5],wv); wv=cmul(wv,B);
    v[3]=cmul(v[3],wv); wv=cmul(wv,B);
    v[7]=cmul(v[7],wv);
    inv256(v, W);
    store8(g_probes + ((size_t)b*P_ + p)*NF + (size_t)my*N_, v, l);
}

__global__ void k_probes_cols(){
    __shared__ float2 tile[2048];
    int blk = blockIdx.x, t = blk & 31, f = blk >> 5;
    int xg0 = t*8;
    int w = threadIdx.x >> 5, l = threadIdx.x & 31;
    WF W = make_wf(l);
    float2* F = g_probes + (size_t)f*NF;
    #pragma unroll
    for (int c = 0; c < 8; c++){
        int e = threadIdx.x + 256*c; int j = e & 7, my = e >> 3;
        tile[TADDR(my,j)] = F[(size_t)my*N_ + xg0 + j];
    }
    __syncthreads();
    float2 v[8];
    #pragma unroll
    for (int r = 0; r < 8; r++) v[r] = tile[TADDR(l+32*r, w)];
    inv256(v, W);
    #pragma unroll
    for (int r = 0; r < 8; r++){
        v[r].x *= (1.0f/256.0f); v[r].y *= (1.0f/256.0f);
        tile[TADDR(l+32*r, w)] = v[r];
    }
    __syncthreads();
    #pragma unroll
    for (int c = 0; c < 8; c++){
        int e = threadIdx.x + 256*c; int j = e & 7, my = e >> 3;
        F[(size_t)my*N_ + xg0 + j] = tile[TADDR(my,j)];
    }
}

// ---------------- rows pass A (ILP2 over p-modes) ----------------
__global__ void k_rows_A(const float* __restrict__ obja, const float* __restrict__ objp,
                         float* __restrict__ pp_out, int z){
    int blk = blockIdx.x, rb = blk & 31, bo = blk >> 5;
    int o = bo & 1, b = bo >> 1;
    int w = threadIdx.x >> 5, l = threadIdx.x & 31;
    int y = rb*8 + w;
    WF W = make_wf(l);
    int cy = g_cy[b], cx = g_cx[b];
    size_t obase = ((size_t)(o*Z_ + z)*OY_ + (size_t)(cy + y))*OY_ + cx;
    float scale = (z == 0) ? 1.0f : (1.0f/256.0f);
    size_t ppbase = ((((size_t)b*O_ + o)*Z_ + z)*N_ + y)*(size_t)N_;
    float2 obj[8];
    #pragma unroll
    for (int r = 0; r < 8; r++){
        int x = l + 32*r;
        float A = obja[obase + x], ph = objp[obase + x];
        float sn, cs; __sincosf(ph, &sn, &cs);
        obj[r] = make_float2(A*cs*scale, A*sn*scale);
        pp_out[ppbase + x] = ph;
    }
    const float2* srcbase = (z == 0)
        ? g_probes + (size_t)b*P_*NF + (size_t)y*N_
        : g_bufB  + (size_t)bo*P_*NF + (size_t)y*N_;
    float2* dstbase = g_bufA + (size_t)bo*P_*NF + (size_t)y*N_;

    #pragma unroll 1
    for (int p = 0; p < P_; p += 2){
        float2 va[8], vb[8];
        load8(va, srcbase + (size_t)p*NF, l);
        load8(vb, srcbase + (size_t)(p+1)*NF, l);
        if (z) inv256_2(va, vb, W);
        #pragma unroll
        for (int r = 0; r < 8; r++){
            va[r] = cmul(va[r], obj[r]);
            vb[r] = cmul(vb[r], obj[r]);
        }
        fwd256_2(va, vb, W);
        store8(dstbase + (size_t)p*NF, va, l);
        store8(dstbase + (size_t)(p+1)*NF, vb, l);
    }
}

// ---------------- cols pass B (16-col tile, ILP2 per warp) ----------------
__global__ void k_cols_H(){
    __shared__ float2 tile[4096];
    int blk = blockIdx.x, t = blk & 15, f = blk >> 4;
    int xg0 = t*16;
    int w = threadIdx.x >> 5, l = threadIdx.x & 31;
    WF W = make_wf(l);
    const float2* s = g_bufA + (size_t)f*NF;
    #pragma unroll
    for (int c = 0; c < 16; c++){
        int e = threadIdx.x + 256*c; int j = e & 15, my = e >> 4;
        tile[TADDR16(my,j)] = s[(size_t)my*N_ + xg0 + j];
    }
    __syncthreads();
    float2 va[8], vb[8];
    #pragma unroll
    for (int r = 0; r < 8; r++){
        va[r] = tile[TADDR16(l+32*r, w)];
        vb[r] = tile[TADDR16(l+32*r, w+8)];
    }
    fwd256_2(va, vb, W);
    const float2* Hc0 = g_Ht + (size_t)(xg0 + w)*N_;
    const float2* Hc1 = g_Ht + (size_t)(xg0 + w + 8)*N_;
    #pragma unroll
    for (int r = 0; r < 8; r++){
        va[r] = cmul(va[r], Hc0[l + 32*r]);
        vb[r] = cmul(vb[r], Hc1[l + 32*r]);
    }
    inv256_2(va, vb, W);
    #pragma unroll
    for (int r = 0; r < 8; r++){
        tile[TADDR16(l+32*r, w)]   = va[r];
        tile[TADDR16(l+32*r, w+8)] = vb[r];
    }
    __syncthreads();
    float2* d = g_bufB + (size_t)f*NF;
    #pragma unroll
    for (int c = 0; c < 16; c++){
        int e = threadIdx.x + 256*c; int j = e & 15, my = e >> 4;
        d[(size_t)my*N_ + xg0 + j] = tile[TADDR16(my,j)];
    }
}

// ---------------- final ----------------
__global__ void k_cols_final(const float* __restrict__ occu, float* __restrict__ dp){
    __shared__ float2 tile[2048];
    int blk = blockIdx.x, t = blk & 31, b = blk >> 5;
    int xg0 = t*8;
    int w = threadIdx.x >> 5, l = threadIdx.x & 31;
    WF W = make_wf(l);
    float acc[8];
    #pragma unroll
    for (int k = 0; k < 8; k++) acc[k] = 0.0f;
    for (int o = 0; o < O_; o++){
        float wt = occu[o];
        for (int p = 0; p < P_; p++){
            const float2* s = g_bufA + ((size_t)((b*O_ + o)*P_ + p))*NF;
            __syncthreads();
            #pragma unroll
            for (int c = 0; c < 8; c++){
                int e = threadIdx.x + 256*c; int j = e & 7, my = e >> 3;
                tile[TADDR(my,j)] = s[(size_t)my*N_ + xg0 + j];
            }
            __syncthreads();
            float2 v[8];
            #pragma unroll
            for (int r = 0; r < 8; r++) v[r] = tile[TADDR(l+32*r, w)];
            fwd256(v, W);
            #pragma unroll
            for (int r = 0; r < 8; r++) acc[r] += wt*(v[r].x*v[r].x + v[r].y*v[r].y);
        }
    }
    int kx = sigx(xg0 + w);
    int xs = (kx + 128) & 255;
    int r5 = rev5(l);
    #pragma unroll
    for (int r = 0; r < 8; r++){
        int ky = rev3c(r) + 8*r5;
        dp[(size_t)b*NF + (size_t)((ky + 128) & 255)*N_ + xs] = acc[r];
    }
}

// ---------------- launch ----------------
extern "C" void kernel_launch(void* const* d_in, const int* in_sizes, int n_in,
                              void* d_out, int out_size){
    const float* obja   = (const float*)d_in[0];
    const float* objp   = (const float*)d_in[1];
    const float* pr     = (const float*)d_in[2];
    const float* pi     = (const float*)d_in[3];
    const float* Hr     = (const float*)d_in[4];
    const float* Hi     = (const float*)d_in[5];
    const float* occu   = (const float*)d_in[6];
    const float* shifts = (const float*)d_in[7];
    const int*   crop   = (const int*)d_in[8];
    const void*  idx    = d_in[9];

    float* dp = (float*)d_out;                    // (NB, 256, 256)
    float* pp = dp + (size_t)NB_ * NF;            // (NB, O, Z, 256, 256)

    k_setup_H<<<256, 256>>>(Hr, Hi, shifts, crop, idx);
    k_probe_rows<<<P_*32, 256>>>(pr, pi);
    k_probe_cols<<<P_*32, 256>>>();
    k_probes_rows<<<NB_*P_*32, 256>>>();
    k_probes_cols<<<NB_*P_*32, 256>>>();

    k_rows_A<<<NB_*O_*32, 256>>>(obja, objp, pp, 0);
    for (int z = 0; z < Z_ - 1; z++){
        k_cols_H<<<NB_*O_*P_*16, 256>>>();
        k_rows_A<<<NB_*O_*32, 256>>>(obja, objp, pp, z + 1);
    }
    k_cols_final<<<NB_*32, 256>>>(occu, dp);
}

// round 13
// speedup vs baseline: 1.3367x; 1.0090x over previous
#include <cuda_runtime.h>

// ---------------- problem constants ----------------
#define O_    2
#define Z_    8
#define OY_   1024
#define P_    8
#define N_    256
#define NB_   32
#define NF    65536
#define TWO_PI 6.28318530717958647692f
#define PI_F  3.14159265358979323846f

// XOR-swizzled column-tile addressing, 8 cols (float2)
#define TADDR(my,j)   ((((my) << 3)) | ((j) ^ (((my) >> 2) & 7)))
// 16-col variant: conflict-free for 128B-row staging AND per-warp column reads
#define TADDR16(my,j) ((((my) << 4)) | ((j) ^ ((my) & 15)))

// ---------------- static device scratch ----------------
__device__ int    g_cy[NB_], g_cx[NB_];
__device__ float  g_sy[NB_], g_sx[NB_];
__device__ float2 g_Ht[(size_t)NF];                                   // H permuted both axes, /256 folded
__device__ __align__(16) float2 g_probeF[(size_t)P_ * NF];
__device__ __align__(16) float2 g_probes[(size_t)NB_ * P_ * NF];
__device__ __align__(16) float2 g_bufA[(size_t)NB_ * O_ * P_ * NF];
__device__ __align__(16) float2 g_bufB[(size_t)NB_ * O_ * P_ * NF];

// ---------------- packed f32x2 complex helpers ----------------
__device__ __forceinline__ float2 cadd(float2 a, float2 b){
    float2 r;
    asm("{\n\t.reg .b64 ra, rb, rr;\n\t"
        "mov.b64 ra, {%2,%3};\n\t"
        "mov.b64 rb, {%4,%5};\n\t"
        "add.rn.f32x2 rr, ra, rb;\n\t"
        "mov.b64 {%0,%1}, rr;\n\t}"
        : "=f"(r.x), "=f"(r.y) : "f"(a.x), "f"(a.y), "f"(b.x), "f"(b.y));
    return r;
}
__device__ __forceinline__ float2 csub(float2 a, float2 b){
    float2 r;
    asm("{\n\t.reg .b64 ra, rb, rn, rr;\n\t"
        "mov.b64 ra, {%2,%3};\n\t"
        "mov.b64 rb, {%4,%5};\n\t"
        "mov.b64 rn, 0xBF800000BF800000;\n\t"
        "fma.rn.f32x2 rr, rb, rn, ra;\n\t"
        "mov.b64 {%0,%1}, rr;\n\t}"
        : "=f"(r.x), "=f"(r.y) : "f"(a.x), "f"(a.y), "f"(b.x), "f"(b.y));
    return r;
}
__device__ __forceinline__ float2 cfma1(float t, float2 v, float2 p){
    float2 r;
    asm("{\n\t.reg .b64 rv, rp, rt, rr;\n\t"
        "mov.b64 rv, {%3,%4};\n\t"
        "mov.b64 rp, {%5,%6};\n\t"
        "mov.b64 rt, {%2,%2};\n\t"
        "fma.rn.f32x2 rr, rv, rt, rp;\n\t"
        "mov.b64 {%0,%1}, rr;\n\t}"
        : "=f"(r.x), "=f"(r.y) : "f"(t), "f"(v.x), "f"(v.y), "f"(p.x), "f"(p.y));
    return r;
}
__device__ __forceinline__ float2 cmul(float2 a, float2 b){ return make_float2(a.x*b.x - a.y*b.y, a.x*b.y + a.y*b.x); }
__device__ __forceinline__ float2 cmulc(float2 t, float2 x){ return make_float2(t.x*x.x + t.y*x.y, t.x*x.y - t.y*x.x); }
__device__ __forceinline__ float2 conjf2(float2 a){ return make_float2(a.x, -a.y); }

__device__ __forceinline__ int rev5(int l){ return (int)(__brev((unsigned)l) >> 27); }
__device__ __forceinline__ int rev3c(int r){ return ((r&1)<<2) | (r&2) | ((r&4)>>2); }
__device__ __forceinline__ int sigma(int m){ return rev3c(m>>5) + 8*rev5(m&31); }
__device__ __forceinline__ int sigx(int q){ return rev3c(2*(q>>6) + (q&1)) + 8*rev5((q>>1)&31); }

__device__ __forceinline__ float2 shflx(float2 v, int d){
    v.x = __shfl_xor_sync(0xffffffffu, v.x, d);
    v.y = __shfl_xor_sync(0xffffffffu, v.y, d);
    return v;
}

// ---------------- per-lane FFT constants ----------------
struct WF { float2 w16, w8, w4, w2, base; float t16, t8, t4, t2, t1; };
__device__ __forceinline__ WF make_wf(int l){
    WF W; float s, c;
    __sincosf(-(TWO_PI/256.0f)*(float)l, &s, &c); W.base = make_float2(c, s);
    __sincosf(-(PI_F/16.0f)*(float)(l&15), &s, &c); W.w16 = (l&16)? make_float2(c,s) : make_float2(1.f,0.f);
    __sincosf(-(PI_F/ 8.0f)*(float)(l& 7), &s, &c); W.w8  = (l& 8)? make_float2(c,s) : make_float2(1.f,0.f);
    __sincosf(-(PI_F/ 4.0f)*(float)(l& 3), &s, &c); W.w4  = (l& 4)? make_float2(c,s) : make_float2(1.f,0.f);
    __sincosf(-(PI_F/ 2.0f)*(float)(l& 1), &s, &c); W.w2  = (l& 2)? make_float2(c,s) : make_float2(1.f,0.f);
    W.t16 = (l&16)? -1.f:1.f;  W.t8 = (l&8)? -1.f:1.f;  W.t4 = (l&4)? -1.f:1.f;
    W.t2  = (l& 2)? -1.f:1.f;  W.t1 = (l&1)? -1.f:1.f;
    return W;
}

#define RC8 0.70710678118654752440f

// DIF-8 in registers: natural in, bitrev3 out
__device__ __forceinline__ void fft8(float2 v[8]){
    float2 t0=cadd(v[0],v[4]), t1=cadd(v[1],v[5]), t2=cadd(v[2],v[6]), t3=cadd(v[3],v[7]);
    float2 u0=csub(v[0],v[4]);
    float2 d1=csub(v[1],v[5]); float2 u1=make_float2(RC8*(d1.x+d1.y), RC8*(d1.y-d1.x));
    float2 d2=csub(v[2],v[6]); float2 u2=make_float2(d2.y, -d2.x);
    float2 d3=csub(v[3],v[7]); float2 u3=make_float2(RC8*(d3.y-d3.x), -RC8*(d3.x+d3.y));
    float2 a0=cadd(t0,t2), a1=cadd(t1,t3), a2=csub(t0,t2);
    float2 dt=csub(t1,t3); float2 a3=make_float2(dt.y,-dt.x);
    float2 b0=cadd(u0,u2), b1=cadd(u1,u3), b2=csub(u0,u2);
    float2 du=csub(u1,u3); float2 b3=make_float2(du.y,-du.x);
    v[0]=cadd(a0,a1); v[1]=csub(a0,a1); v[2]=cadd(a2,a3); v[3]=csub(a2,a3);
    v[4]=cadd(b0,b1); v[5]=csub(b0,b1); v[6]=cadd(b2,b3); v[7]=csub(b2,b3);
}

// DIT-8 in registers: bitrev3 in, natural out, e^{+}
__device__ __forceinline__ void ifft8(float2 v[8]){
    float2 s0=cadd(v[0],v[1]), d0=csub(v[0],v[1]);
    float2 s1=cadd(v[2],v[3]), d1=csub(v[2],v[3]);
    float2 s2=cadd(v[4],v[5]), d2=csub(v[4],v[5]);
    float2 s3=cadd(v[6],v[7]), d3=csub(v[6],v[7]);
    float2 id1=make_float2(-d1.y,d1.x), id3=make_float2(-d3.y,d3.x);
    float2 p0=cadd(s0,s1), p2=csub(s0,s1), p1=cadd(d0,id1), p3=csub(d0,id1);
    float2 q0=cadd(s2,s3), q2=csub(s2,s3), q1=cadd(d2,id3), q3=csub(d2,id3);
    float2 w1q=make_float2(RC8*(q1.x-q1.y), RC8*(q1.x+q1.y));
    float2 iq2=make_float2(-q2.y,q2.x);
    float2 w3q=make_float2(-RC8*(q3.x+q3.y), RC8*(q3.x-q3.y));
    v[0]=cadd(p0,q0);  v[4]=csub(p0,q0);
    v[1]=cadd(p1,w1q); v[5]=csub(p1,w1q);
    v[2]=cadd(p2,iq2); v[6]=csub(p2,iq2);
    v[3]=cadd(p3,w3q); v[7]=csub(p3,w3q);
}

__device__ __forceinline__ void twchain(float2 v[8], float2 base){
    float2 w = base;
    v[4]=cmul(v[4],w); w=cmul(w,base);
    v[2]=cmul(v[2],w); w=cmul(w,base);
    v[6]=cmul(v[6],w); w=cmul(w,base);
    v[1]=cmul(v[1],w); w=cmul(w,base);
    v[5]=cmul(v[5],w); w=cmul(w,base);
    v[3]=cmul(v[3],w); w=cmul(w,base);
    v[7]=cmul(v[7],w);
}

// ---- single-chain cross-lane stages ----
__device__ __forceinline__ void fstage(float2 v[8], int D, float2 w, float t){
    #pragma unroll
    for (int k = 0; k < 8; k++){
        float2 p = shflx(v[k], D);
        v[k] = cmul(w, cfma1(t, v[k], p));
    }
}
__device__ __forceinline__ void fstage1(float2 v[8], float t){
    #pragma unroll
    for (int k = 0; k < 8; k++){
        float2 p = shflx(v[k], 1);
        v[k] = cfma1(t, v[k], p);
    }
}

__device__ __forceinline__ void fwd256(float2 v[8], const WF& W){
    fft8(v);
    twchain(v, W.base);
    fstage(v,16,W.w16,W.t16);
    fstage(v, 8,W.w8 ,W.t8 );
    fstage(v, 4,W.w4 ,W.t4 );
    fstage(v, 2,W.w2 ,W.t2 );
    fstage1(v, W.t1);
}

// ---- paired (ILP2) stages: two independent chains interleaved ----
__device__ __forceinline__ void fstage2(float2 a[8], float2 b[8], int D, float2 w, float t){
    #pragma unroll
    for (int k = 0; k < 8; k++){
        float2 pa = shflx(a[k], D);
        float2 pb = shflx(b[k], D);
        a[k] = cmul(w, cfma1(t, a[k], pa));
        b[k] = cmul(w, cfma1(t, b[k], pb));
    }
}
__device__ __forceinline__ void fstage1_2(float2 a[8], float2 b[8], float t){
    #pragma unroll
    for (int k = 0; k < 8; k++){
        float2 pa = shflx(a[k], 1);
        float2 pb = shflx(b[k], 1);
        a[k] = cfma1(t, a[k], pa);
        b[k] = cfma1(t, b[k], pb);
    }
}
__device__ __forceinline__ void istage2(float2 a[8], float2 b[8], int D, float2 w, float t){
    #pragma unroll
    for (int k = 0; k < 8; k++){
        float2 ya = cmulc(w, a[k]);
        float2 yb = cmulc(w, b[k]);
        float2 pa = shflx(ya, D);
        float2 pb = shflx(yb, D);
        a[k] = cfma1(t, ya, pa);
        b[k] = cfma1(t, yb, pb);
    }
}
__device__ __forceinline__ void istage1_2(float2 a[8], float2 b[8], float t){
    #pragma unroll
    for (int k = 0; k < 8; k++){
        float2 pa = shflx(a[k], 1);
        float2 pb = shflx(b[k], 1);
        a[k] = cfma1(t, a[k], pa);
        b[k] = cfma1(t, b[k], pb);
    }
}
__device__ __forceinline__ void fwd256_2(float2 a[8], float2 b[8], const WF& W){
    fft8(a); fft8(b);
    twchain(a, W.base); twchain(b, W.base);
    fstage2(a,b,16,W.w16,W.t16);
    fstage2(a,b, 8,W.w8 ,W.t8 );
    fstage2(a,b, 4,W.w4 ,W.t4 );
    fstage2(a,b, 2,W.w2 ,W.t2 );
    fstage1_2(a,b, W.t1);
}
__device__ __forceinline__ void inv256_2(float2 a[8], float2 b[8], const WF& W){
    istage1_2(a,b, W.t1);
    istage2(a,b, 2,W.w2 ,W.t2 );
    istage2(a,b, 4,W.w4 ,W.t4 );
    istage2(a,b, 8,W.w8 ,W.t8 );
    istage2(a,b,16,W.w16,W.t16);
    float2 cb = conjf2(W.base);
    twchain(a, cb); twchain(b, cb);
    ifft8(a); ifft8(b);
}

// ---- float4-packed row I/O ----
__device__ __forceinline__ void load8(float2 v[8], const float2* row, int l){
    const float4* r4 = (const float4*)row;
    #pragma unroll
    for (int rp = 0; rp < 4; rp++){
        float4 q = r4[l + 32*rp];
        v[2*rp]   = make_float2(q.x, q.y);
        v[2*rp+1] = make_float2(q.z, q.w);
    }
}
__device__ __forceinline__ void store8(float2* row, const float2 v[8], int l){
    float4* r4 = (float4*)row;
    #pragma unroll
    for (int rp = 0; rp < 4; rp++)
        r4[l + 32*rp] = make_float4(v[2*rp].x, v[2*rp].y, v[2*rp+1].x, v[2*rp+1].y);
}

// ---------------- setup ----------------
__global__ void k_setup_H(const float* __restrict__ Hr, const float* __restrict__ Hi,
                          const float* __restrict__ shifts,
                          const int*   __restrict__ crop,
                          const void*  __restrict__ idxraw){
    int idx = blockIdx.x*256 + threadIdx.x;
    int my = idx & 255, mx = idx >> 8;
    int ky = sigma(my), kx = sigx(mx);
    size_t hsrc = (size_t)ky*N_ + kx;
    g_Ht[(size_t)mx*N_ + my] = make_float2(Hr[hsrc]*(1.0f/256.0f), Hi[hsrc]*(1.0f/256.0f));
    if (idx == 0){
        const int* w = (const int*)idxraw;
        int orr = 0;
        for (int k = 1; k < NB_; k += 2) orr |= w[k];
        bool is64 = (orr == 0);
        for (int b = 0; b < NB_; b++){
            int id = is64 ? (int)(((const long long*)idxraw)[b]) : w[b];
            g_cy[b] = crop[2*id];
            g_cx[b] = crop[2*id + 1];
            g_sy[b] = shifts[2*id];
            g_sx[b] = shifts[2*id + 1];
        }
    }
}

// ---------------- probe fft2 ----------------
__global__ void k_probe_rows(const float* __restrict__ pr, const float* __restrict__ pi){
    int blk = blockIdx.x, rb = blk & 31, p = blk >> 5;
    int w = threadIdx.x >> 5, l = threadIdx.x & 31;
    int y = rb*8 + w;
    WF W = make_wf(l);
    size_t base = ((size_t)p*N_ + y)*N_;
    float2 v[8];
    #pragma unroll
    for (int r = 0; r < 8; r++){ int x = l + 32*r; v[r] = make_float2(pr[base+x], pi[base+x]); }
    fwd256(v, W);
    store8(g_probeF + base, v, l);
}

__global__ void k_probe_cols(){
    __shared__ float2 tile[2048];
    int blk = blockIdx.x, t = blk & 31, p = blk >> 5;
    int xg0 = t*8;
    int w = threadIdx.x >> 5, l = threadIdx.x & 31;
    WF W = make_wf(l);
    float2* F = g_probeF + (size_t)p*NF;
    #pragma unroll
    for (int c = 0; c < 8; c++){
        int e = threadIdx.x + 256*c; int j = e & 7, my = e >> 3;
        tile[TADDR(my,j)] = F[(size_t)my*N_ + xg0 + j];
    }
    __syncthreads();
    float2 v[8];
    #pragma unroll
    for (int r = 0; r < 8; r++) v[r] = tile[TADDR(l+32*r, w)];
    fwd256(v, W);
    #pragma unroll
    for (int r = 0; r < 8; r++) tile[TADDR(l+32*r, w)] = v[r];
    __syncthreads();
    #pragma unroll
    for (int c = 0; c < 8; c++){
        int e = threadIdx.x + 256*c; int j = e & 7, my = e >> 3;
        F[(size_t)my*N_ + xg0 + j] = tile[TADDR(my,j)];
    }
}

// ---------------- shifted probes: ramp + row inverse, ILP2 over p, setup amortized ----------------
__global__ void k_probes_rows(){
    int blk = blockIdx.x, rb = blk & 31, b = blk >> 5;
    int w = threadIdx.x >> 5, l = threadIdx.x & 31;
    int my = rb*8 + w;
    WF W = make_wf(l);
    float sy = g_sy[b], sx = g_sx[b];
    int ky = sigma(my);
    float f = sy*(float)ky*(1.0f/256.0f) + sx*(float)rev5(l)*(1.0f/32.0f);
    f -= rintf(f);
    float s, c; __sincosf(-TWO_PI*f, &s, &c);
    float2 C = make_float2(c*(1.0f/256.0f), s*(1.0f/256.0f));
    float fb = sx*(1.0f/256.0f); fb -= rintf(fb);
    __sincosf(-TWO_PI*fb, &s, &c); float2 B = make_float2(c, s);
    // chain values per register (bin order 0,4,2,6,1,5,3,7)
    float2 cw[8];
    float2 wv = C;
    cw[0]=wv; wv=cmul(wv,B);
    cw[4]=wv; wv=cmul(wv,B);
    cw[2]=wv; wv=cmul(wv,B);
    cw[6]=wv; wv=cmul(wv,B);
    cw[1]=wv; wv=cmul(wv,B);
    cw[5]=wv; wv=cmul(wv,B);
    cw[3]=wv; wv=cmul(wv,B);
    cw[7]=wv;
    const float2* srcbase = g_probeF + (size_t)my*N_;
    float2* dstbase = g_probes + (size_t)b*P_*NF + (size_t)my*N_;
    #pragma unroll 1
    for (int p = 0; p < P_; p += 2){
        float2 va[8], vb[8];
        load8(va, srcbase + (size_t)p*NF, l);
        load8(vb, srcbase + (size_t)(p+1)*NF, l);
        #pragma unroll
        for (int r = 0; r < 8; r++){
            va[r] = cmul(va[r], cw[r]);
            vb[r] = cmul(vb[r], cw[r]);
        }
        inv256_2(va, vb, W);
        store8(dstbase + (size_t)p*NF, va, l);
        store8(dstbase + (size_t)(p+1)*NF, vb, l);
    }
}

// ---------------- shifted probes: col inverse, 16-col tile ILP2 ----------------
__global__ void k_probes_cols(){
    __shared__ float2 tile[4096];
    int blk = blockIdx.x, t = blk & 15, f = blk >> 4;
    int xg0 = t*16;
    int w = threadIdx.x >> 5, l = threadIdx.x & 31;
    WF W = make_wf(l);
    float2* F = g_probes + (size_t)f*NF;
    #pragma unroll
    for (int c = 0; c < 16; c++){
        int e = threadIdx.x + 256*c; int j = e & 15, my = e >> 4;
        tile[TADDR16(my,j)] = F[(size_t)my*N_ + xg0 + j];
    }
    __syncthreads();
    float2 va[8], vb[8];
    #pragma unroll
    for (int r = 0; r < 8; r++){
        va[r] = tile[TADDR16(l+32*r, w)];
        vb[r] = tile[TADDR16(l+32*r, w+8)];
    }
    inv256_2(va, vb, W);
    #pragma unroll
    for (int r = 0; r < 8; r++){
        va[r].x *= (1.0f/256.0f); va[r].y *= (1.0f/256.0f);
        vb[r].x *= (1.0f/256.0f); vb[r].y *= (1.0f/256.0f);
        tile[TADDR16(l+32*r, w)]   = va[r];
        tile[TADDR16(l+32*r, w+8)] = vb[r];
    }
    __syncthreads();
    #pragma unroll
    for (int c = 0; c < 16; c++){
        int e = threadIdx.x + 256*c; int j = e & 15, my = e >> 4;
        F[(size_t)my*N_ + xg0 + j] = tile[TADDR16(my,j)];
    }
}

// ---------------- rows pass A (ILP2 over p-modes) ----------------
__global__ void k_rows_A(const float* __restrict__ obja, const float* __restrict__ objp,
                         float* __restrict__ pp_out, int z){
    int blk = blockIdx.x, rb = blk & 31, bo = blk >> 5;
    int o = bo & 1, b = bo >> 1;
    int w = threadIdx.x >> 5, l = threadIdx.x & 31;
    int y = rb*8 + w;
    WF W = make_wf(l);
    int cy = g_cy[b], cx = g_cx[b];
    size_t obase = ((size_t)(o*Z_ + z)*OY_ + (size_t)(cy + y))*OY_ + cx;
    float scale = (z == 0) ? 1.0f : (1.0f/256.0f);
    size_t ppbase = ((((size_t)b*O_ + o)*Z_ + z)*N_ + y)*(size_t)N_;
    float2 obj[8];
    #pragma unroll
    for (int r = 0; r < 8; r++){
        int x = l + 32*r;
        float A = obja[obase + x], ph = objp[obase + x];
        float sn, cs; __sincosf(ph, &sn, &cs);
        obj[r] = make_float2(A*cs*scale, A*sn*scale);
        pp_out[ppbase + x] = ph;
    }
    const float2* srcbase = (z == 0)
        ? g_probes + (size_t)b*P_*NF + (size_t)y*N_
        : g_bufB  + (size_t)bo*P_*NF + (size_t)y*N_;
    float2* dstbase = g_bufA + (size_t)bo*P_*NF + (size_t)y*N_;

    #pragma unroll 1
    for (int p = 0; p < P_; p += 2){
        float2 va[8], vb[8];
        load8(va, srcbase + (size_t)p*NF, l);
        load8(vb, srcbase + (size_t)(p+1)*NF, l);
        if (z) inv256_2(va, vb, W);
        #pragma unroll
        for (int r = 0; r < 8; r++){
            va[r] = cmul(va[r], obj[r]);
            vb[r] = cmul(vb[r], obj[r]);
        }
        fwd256_2(va, vb, W);
        store8(dstbase + (size_t)p*NF, va, l);
        store8(dstbase + (size_t)(p+1)*NF, vb, l);
    }
}

// ---------------- cols pass B (16-col tile, ILP2 per warp) ----------------
__global__ void k_cols_H(){
    __shared__ float2 tile[4096];
    int blk = blockIdx.x, t = blk & 15, f = blk >> 4;
    int xg0 = t*16;
    int w = threadIdx.x >> 5, l = threadIdx.x & 31;
    WF W = make_wf(l);
    const float2* s = g_bufA + (size_t)f*NF;
    #pragma unroll
    for (int c = 0; c < 16; c++){
        int e = threadIdx.x + 256*c; int j = e & 15, my = e >> 4;
        tile[TADDR16(my,j)] = s[(size_t)my*N_ + xg0 + j];
    }
    __syncthreads();
    float2 va[8], vb[8];
    #pragma unroll
    for (int r = 0; r < 8; r++){
        va[r] = tile[TADDR16(l+32*r, w)];
        vb[r] = tile[TADDR16(l+32*r, w+8)];
    }
    fwd256_2(va, vb, W);
    const float2* Hc0 = g_Ht + (size_t)(xg0 + w)*N_;
    const float2* Hc1 = g_Ht + (size_t)(xg0 + w + 8)*N_;
    #pragma unroll
    for (int r = 0; r < 8; r++){
        va[r] = cmul(va[r], Hc0[l + 32*r]);
        vb[r] = cmul(vb[r], Hc1[l + 32*r]);
    }
    inv256_2(va, vb, W);
    #pragma unroll
    for (int r = 0; r < 8; r++){
        tile[TADDR16(l+32*r, w)]   = va[r];
        tile[TADDR16(l+32*r, w+8)] = vb[r];
    }
    __syncthreads();
    float2* d = g_bufB + (size_t)f*NF;
    #pragma unroll
    for (int c = 0; c < 16; c++){
        int e = threadIdx.x + 256*c; int j = e & 15, my = e >> 4;
        d[(size_t)my*N_ + xg0 + j] = tile[TADDR16(my,j)];
    }
}

// ---------------- final: twin tiles, ILP2 over p pairs ----------------
__global__ void k_cols_final(const float* __restrict__ occu, float* __restrict__ dp){
    __shared__ float2 tA[2048];
    __shared__ float2 tB[2048];
    int blk = blockIdx.x, t = blk & 31, b = blk >> 5;
    int xg0 = t*8;
    int w = threadIdx.x >> 5, l = threadIdx.x & 31;
    WF W = make_wf(l);
    float acc[8];
    #pragma unroll
    for (int k = 0; k < 8; k++) acc[k] = 0.0f;
    for (int o = 0; o < O_; o++){
        float wt = occu[o];
        #pragma unroll 1
        for (int p = 0; p < P_; p += 2){
            const float2* sA = g_bufA + ((size_t)((b*O_ + o)*P_ + p))*NF;
            const float2* sB = sA + (size_t)NF;
            __syncthreads();
            #pragma unroll
            for (int c = 0; c < 8; c++){
                int e = threadIdx.x + 256*c; int j = e & 7, my = e >> 3;
                tA[TADDR(my,j)] = sA[(size_t)my*N_ + xg0 + j];
                tB[TADDR(my,j)] = sB[(size_t)my*N_ + xg0 + j];
            }
            __syncthreads();
            float2 va[8], vb[8];
            #pragma unroll
            for (int r = 0; r < 8; r++){
                va[r] = tA[TADDR(l+32*r, w)];
                vb[r] = tB[TADDR(l+32*r, w)];
            }
            fwd256_2(va, vb, W);
            #pragma unroll
            for (int r = 0; r < 8; r++)
                acc[r] += wt*(va[r].x*va[r].x + va[r].y*va[r].y
                            + vb[r].x*vb[r].x + vb[r].y*vb[r].y);
        }
    }
    int kx = sigx(xg0 + w);
    int xs = (kx + 128) & 255;
    int r5 = rev5(l);
    #pragma unroll
    for (int r = 0; r < 8; r++){
        int ky = rev3c(r) + 8*r5;
        dp[(size_t)b*NF + (size_t)((ky + 128) & 255)*N_ + xs] = acc[r];
    }
}

// ---------------- launch ----------------
extern "C" void kernel_launch(void* const* d_in, const int* in_sizes, int n_in,
                              void* d_out, int out_size){
    const float* obja   = (const float*)d_in[0];
    const float* objp   = (const float*)d_in[1];
    const float* pr     = (const float*)d_in[2];
    const float* pi     = (const float*)d_in[3];
    const float* Hr     = (const float*)d_in[4];
    const float* Hi     = (const float*)d_in[5];
    const float* occu   = (const float*)d_in[6];
    const float* shifts = (const float*)d_in[7];
    const int*   crop   = (const int*)d_in[8];
    const void*  idx    = d_in[9];

    float* dp = (float*)d_out;                    // (NB, 256, 256)
    float* pp = dp + (size_t)NB_ * NF;            // (NB, O, Z, 256, 256)

    k_setup_H<<<256, 256>>>(Hr, Hi, shifts, crop, idx);
    k_probe_rows<<<P_*32, 256>>>(pr, pi);
    k_probe_cols<<<P_*32, 256>>>();
    k_probes_rows<<<NB_*32, 256>>>();
    k_probes_cols<<<NB_*P_*16, 256>>>();

    k_rows_A<<<NB_*O_*32, 256>>>(obja, objp, pp, 0);
    for (int z = 0; z < Z_ - 1; z++){
        k_cols_H<<<NB_*O_*P_*16, 256>>>();
        k_rows_A<<<NB_*O_*32, 256>>>(obja, objp, pp, z + 1);
    }
    k_cols_final<<<NB_*32, 256>>>(occu, dp);
}